// round 5
// baseline (speedup 1.0000x reference)
#include <cuda_runtime.h>
#include <cuda_bf16.h>

// ---------------- problem constants ----------------
#define B_    2
#define T_    8192
#define D_    1024
#define H_    4
#define HD_   256
#define C_    64
#define N_    128
#define BH_   8

typedef unsigned long long ull;

// ---------------- f32x2 helpers (PTX-only on sm_103a) ----------------
__device__ __forceinline__ ull pk2(float a, float b) {
    ull r; asm("mov.b64 %0, {%1, %2};" : "=l"(r) : "f"(a), "f"(b)); return r;
}
__device__ __forceinline__ float2 upk2(ull v) {
    float2 f; asm("mov.b64 {%0, %1}, %2;" : "=f"(f.x), "=f"(f.y) : "l"(v)); return f;
}
__device__ __forceinline__ ull fma2(ull a, ull b, ull c) {
    ull d; asm("fma.rn.f32x2 %0, %1, %2, %3;" : "=l"(d) : "l"(a), "l"(b), "l"(c)); return d;
}
__device__ __forceinline__ ull add2(ull a, ull b) {
    ull d; asm("add.rn.f32x2 %0, %1, %2;" : "=l"(d) : "l"(a), "l"(b)); return d;
}
__device__ __forceinline__ ull mul2(ull a, ull b) {
    ull d; asm("mul.rn.f32x2 %0, %1, %2;" : "=l"(d) : "l"(a), "l"(b)); return d;
}
#define SGN2 0x8000000080000000ULL

__device__ __forceinline__ unsigned smem_u32(const void* p) {
    unsigned a;
    asm("{ .reg .u64 t; cvta.to.shared.u64 t, %1; cvt.u32.u64 %0, t; }" : "=r"(a) : "l"(p));
    return a;
}

// ---------------- device scratch (no allocation allowed) ----------------
__device__ float g_v[(size_t)B_ * T_ * D_];            // x @ Ww^T, (b*T+t, D) layout
__device__ float g_rk[(size_t)BH_ * T_ * HD_];         // normalized keys, (bh, t, d)
__device__ float g_vcorr[(size_t)BH_ * N_ * C_ * HD_]; // A @ v
__device__ float g_wkcorr[(size_t)BH_ * N_ * C_ * HD_];// A @ wk
__device__ float g_intra[(size_t)BH_ * N_ * C_ * C_];  // strict(rk wk^T * L)
__device__ float g_o[(size_t)B_ * T_ * D_];            // alpha * o, (b*T+t, D)
__device__ float g_gpow[H_][C_ + 1];                   // gamma^0..gamma^64
__device__ float g_alpha[H_];

// bf16 copies for tensor-core GEMMs
__device__ __nv_bfloat16 g_xb [(size_t)B_ * T_ * D_];
__device__ __nv_bfloat16 g_ob [(size_t)B_ * T_ * D_];
__device__ __nv_bfloat16 g_Wwb[(size_t)D_ * D_];
__device__ __nv_bfloat16 g_Wrb[(size_t)D_ * D_];

// ---------------- setup ----------------
__global__ void setup_kernel(const float* __restrict__ decay,
                             const float* __restrict__ log_alpha) {
    int h = threadIdx.x;
    if (h < H_) {
        float g = 1.f / (1.f + expf(-decay[h]));
        g_alpha[h] = expf(log_alpha[h]);
        float p = 1.f;
        for (int i = 0; i <= C_; i++) { g_gpow[h][i] = p; p *= g; }
    }
}

// ---------------- f32 -> bf16 conversion (8 elems/thread) ----------------
__global__ __launch_bounds__(256) void conv_bf16(const float* __restrict__ in,
                                                 __nv_bfloat16* __restrict__ out) {
    size_t i = ((size_t)blockIdx.x * 256 + threadIdx.x) * 8;
    float4 a = *(const float4*)(in + i);
    float4 b = *(const float4*)(in + i + 4);
    __nv_bfloat162 r0 = __floats2bfloat162_rn(a.x, a.y);
    __nv_bfloat162 r1 = __floats2bfloat162_rn(a.z, a.w);
    __nv_bfloat162 r2 = __floats2bfloat162_rn(b.x, b.y);
    __nv_bfloat162 r3 = __floats2bfloat162_rn(b.z, b.w);
    uint4 pk;
    pk.x = *(unsigned*)&r0; pk.y = *(unsigned*)&r1;
    pk.z = *(unsigned*)&r2; pk.w = *(unsigned*)&r3;
    *(uint4*)(out + i) = pk;
}

// ---------------- rk: normalize per head, store (bh,t,d) ----------------
__global__ __launch_bounds__(256) void rk_kernel(const float* __restrict__ x) {
    int warp = threadIdx.x >> 5, lane = threadIdx.x & 31;
    int row = blockIdx.x * 8 + warp;            // (b*T+t)*H + h, total 65536
    int h  = row & (H_ - 1);
    int bt = row >> 2;
    const float* xp = x + (size_t)bt * D_ + h * HD_ + lane * 8;
    float4 v0 = *(const float4*)(xp);
    float4 v1 = *(const float4*)(xp + 4);
    float ss = v0.x*v0.x + v0.y*v0.y + v0.z*v0.z + v0.w*v0.w
             + v1.x*v1.x + v1.y*v1.y + v1.z*v1.z + v1.w*v1.w;
    #pragma unroll
    for (int o = 16; o; o >>= 1) ss += __shfl_xor_sync(0xffffffffu, ss, o);
    float inv = 1.f / fmaxf(sqrtf(ss), 1e-12f);
    int b = bt >> 13, t = bt & (T_ - 1);
    float* rp = g_rk + ((size_t)(b * H_ + h) * T_ + t) * HD_ + lane * 8;
    *(float4*)(rp)     = make_float4(v0.x*inv, v0.y*inv, v0.z*inv, v0.w*inv);
    *(float4*)(rp + 4) = make_float4(v1.x*inv, v1.y*inv, v1.z*inv, v1.w*inv);
}

// ---------------- bf16 tensor-core GEMM (TN): C = (Cin?Cin:0) + A @ W^T -------
// M=16384, N=1024, K=1024. CTA 128x128, 256 thr, warp 32x64, K-stage 32.
#define RSE 40   // smem row stride in bf16 elements (80 bytes; conflict-free ldmatrix)
__global__ __launch_bounds__(256) void gemm_bf16_tn(const __nv_bfloat16* __restrict__ A,
                                                    const __nv_bfloat16* __restrict__ W,
                                                    const float* __restrict__ Cin,
                                                    float* __restrict__ Cout) {
    __shared__ __nv_bfloat16 As[128 * RSE];
    __shared__ __nv_bfloat16 Bs[128 * RSE];
    const int tid = threadIdx.x;
    const int bm = blockIdx.y * 128, bn = blockIdx.x * 128;
    const int wid = tid >> 5, lane = tid & 31;
    const int wm = (wid & 3) * 32, wn = (wid >> 2) * 64;

    // gmem staging: each thread loads 2x 16B (rows r, r+64; k-offset (tid&3)*8)
    const int lr = tid >> 2, lk = (tid & 3) * 8;
    const __nv_bfloat16* Ap0 = A + (size_t)(bm + lr) * D_ + lk;
    const __nv_bfloat16* Ap1 = A + (size_t)(bm + lr + 64) * D_ + lk;
    const __nv_bfloat16* Wp0 = W + (size_t)(bn + lr) * D_ + lk;
    const __nv_bfloat16* Wp1 = W + (size_t)(bn + lr + 64) * D_ + lk;

    // ldmatrix lane address templates (bytes)
    const unsigned a_base = smem_u32(As) +
        (unsigned)((wm + (lane & 7) + ((lane >> 3) & 1) * 8) * (RSE * 2) + (lane >> 4) * 16);
    const unsigned b_base = smem_u32(Bs) +
        (unsigned)((wn + (lane & 7) + ((lane >> 4) & 1) * 8) * (RSE * 2) + ((lane >> 3) & 1) * 16);

    float acc[2][8][4];
    #pragma unroll
    for (int mt = 0; mt < 2; mt++)
        #pragma unroll
        for (int nt = 0; nt < 8; nt++)
            #pragma unroll
            for (int q = 0; q < 4; q++) acc[mt][nt][q] = 0.f;

    uint4 pa0 = *(const uint4*)(Ap0), pa1 = *(const uint4*)(Ap1);
    uint4 pb0 = *(const uint4*)(Wp0), pb1 = *(const uint4*)(Wp1);

    for (int k0 = 0; k0 < D_; k0 += 32) {
        __syncthreads();
        *(uint4*)&As[lr * RSE + lk]        = pa0;
        *(uint4*)&As[(lr + 64) * RSE + lk] = pa1;
        *(uint4*)&Bs[lr * RSE + lk]        = pb0;
        *(uint4*)&Bs[(lr + 64) * RSE + lk] = pb1;
        __syncthreads();
        if (k0 + 32 < D_) {
            pa0 = *(const uint4*)(Ap0 + k0 + 32);
            pa1 = *(const uint4*)(Ap1 + k0 + 32);
            pb0 = *(const uint4*)(Wp0 + k0 + 32);
            pb1 = *(const uint4*)(Wp1 + k0 + 32);
        }
        #pragma unroll
        for (int kk = 0; kk < 2; kk++) {
            unsigned ka = a_base + kk * 32;
            unsigned kb = b_base + kk * 32;
            unsigned af[2][4], bf[4][4];
            #pragma unroll
            for (int mt = 0; mt < 2; mt++) {
                unsigned ad = ka + mt * 16 * (RSE * 2);
                asm volatile("ldmatrix.sync.aligned.m8n8.x4.shared.b16 {%0,%1,%2,%3}, [%4];"
                    : "=r"(af[mt][0]), "=r"(af[mt][1]), "=r"(af[mt][2]), "=r"(af[mt][3])
                    : "r"(ad));
            }
            #pragma unroll
            for (int j = 0; j < 4; j++) {
                unsigned bd = kb + j * 16 * (RSE * 2);
                asm volatile("ldmatrix.sync.aligned.m8n8.x4.shared.b16 {%0,%1,%2,%3}, [%4];"
                    : "=r"(bf[j][0]), "=r"(bf[j][1]), "=r"(bf[j][2]), "=r"(bf[j][3])
                    : "r"(bd));
            }
            #pragma unroll
            for (int mt = 0; mt < 2; mt++)
                #pragma unroll
                for (int nt = 0; nt < 8; nt++) {
                    unsigned b0 = bf[nt >> 1][(nt & 1) * 2 + 0];
                    unsigned b1 = bf[nt >> 1][(nt & 1) * 2 + 1];
                    asm volatile(
                        "mma.sync.aligned.m16n8k16.row.col.f32.bf16.bf16.f32 "
                        "{%0,%1,%2,%3}, {%4,%5,%6,%7}, {%8,%9}, {%0,%1,%2,%3};"
                        : "+f"(acc[mt][nt][0]), "+f"(acc[mt][nt][1]),
                          "+f"(acc[mt][nt][2]), "+f"(acc[mt][nt][3])
                        : "r"(af[mt][0]), "r"(af[mt][1]), "r"(af[mt][2]), "r"(af[mt][3]),
                          "r"(b0), "r"(b1));
                }
        }
    }

    // epilogue
    const int rr = lane >> 2, cc = (lane & 3) * 2;
    #pragma unroll
    for (int mt = 0; mt < 2; mt++) {
        int row = bm + wm + mt * 16 + rr;
        #pragma unroll
        for (int nt = 0; nt < 8; nt++) {
            int col = bn + wn + nt * 8 + cc;
            float2 lo = make_float2(acc[mt][nt][0], acc[mt][nt][1]);
            float2 hi = make_float2(acc[mt][nt][2], acc[mt][nt][3]);
            if (Cin) {
                float2 c0 = *(const float2*)(Cin + (size_t)row * D_ + col);
                float2 c1 = *(const float2*)(Cin + (size_t)(row + 8) * D_ + col);
                lo.x += c0.x; lo.y += c0.y; hi.x += c1.x; hi.y += c1.y;
            }
            *(float2*)(Cout + (size_t)row * D_ + col)       = lo;
            *(float2*)(Cout + (size_t)(row + 8) * D_ + col) = hi;
        }
    }
}

// ---------------- chunk prep: W/intra + forward substitution ----------------
__global__ __launch_bounds__(256) void prep_kernel() {
    __shared__ float wkT[16 * 68];
    __shared__ float rkT[16 * 68];
    __shared__ float Wl[64 * 65];
    __shared__ float gp_s[C_ + 1];

    const int tid = threadIdx.x;
    const int n  = blockIdx.x & (N_ - 1);
    const int bh = blockIdx.x >> 7;
    const int b  = bh >> 2, h = bh & 3;
    const int tx = tid & 15, ty = tid >> 4;

    if (tid <= C_) gp_s[tid] = g_gpow[h][tid];

    ull accW[4][2], accR[4][2];
    #pragma unroll
    for (int a = 0; a < 4; a++) { accW[a][0]=0; accW[a][1]=0; accR[a][0]=0; accR[a][1]=0; }

    // -------- phase 1: W = wk wk^T, R = rk wk^T --------
    for (int ks = 0; ks < 16; ks++) {
        int k0 = ks * 16;
        __syncthreads();
        #pragma unroll
        for (int e = 0; e < 4; e++) {
            int q = tid + e * 256;
            int kk = q & 15, j = q >> 4;
            rkT[kk*68 + j] = g_rk[((size_t)bh*T_ + n*C_ + j) * HD_ + k0 + kk];
            int tw = n*C_ + j - 1;
            wkT[kk*68 + j] = (tw >= 0)
                ? g_rk[((size_t)bh*T_ + tw) * HD_ + k0 + kk] : 0.f;
        }
        __syncthreads();
        #pragma unroll
        for (int kk = 0; kk < 16; kk++) {
            float4 wa = *(const float4*)&wkT[kk*68 + ty*4];
            float4 ra = *(const float4*)&rkT[kk*68 + ty*4];
            ulonglong2 wb = *(const ulonglong2*)&wkT[kk*68 + tx*4];
            ull wa2[4] = {pk2(wa.x,wa.x), pk2(wa.y,wa.y), pk2(wa.z,wa.z), pk2(wa.w,wa.w)};
            ull ra2[4] = {pk2(ra.x,ra.x), pk2(ra.y,ra.y), pk2(ra.z,ra.z), pk2(ra.w,ra.w)};
            #pragma unroll
            for (int a = 0; a < 4; a++) {
                accW[a][0] = fma2(wa2[a], wb.x, accW[a][0]);
                accW[a][1] = fma2(wa2[a], wb.y, accW[a][1]);
                accR[a][0] = fma2(ra2[a], wb.x, accR[a][0]);
                accR[a][1] = fma2(ra2[a], wb.y, accR[a][1]);
            }
        }
    }
    // write masked W*L to smem, masked R*L to global
    size_t ib = ((size_t)(bh * N_ + n)) * C_;
    #pragma unroll
    for (int a = 0; a < 4; a++) {
        int i = ty*4 + a;
        float2 w0 = upk2(accW[a][0]), w1 = upk2(accW[a][1]);
        float2 r0 = upk2(accR[a][0]), r1 = upk2(accR[a][1]);
        float wv[4] = {w0.x, w0.y, w1.x, w1.y};
        float rv[4] = {r0.x, r0.y, r1.x, r1.y};
        #pragma unroll
        for (int q = 0; q < 4; q++) {
            int j = tx*4 + q;
            float lg = (j < i) ? gp_s[i - j] : 0.f;
            Wl[i*65 + j] = wv[q] * lg;
            g_intra[(ib + i) * C_ + j] = rv[q] * lg;
        }
    }
    __syncthreads();

    // -------- phase 2: forward substitution for v and wk (packed f32x2) -------
    const int c = tid;
    ull bvw[C_];
    #pragma unroll
    for (int i = 0; i < C_; i++) {
        float bv = g_v[((size_t)b*T_ + n*C_ + i) * D_ + h*HD_ + c];
        int tw = n*C_ + i - 1;
        float bw = (tw >= 0) ? g_rk[((size_t)bh*T_ + tw) * HD_ + c] : 0.f;
        bvw[i] = pk2(bv, bw);
    }
    #pragma unroll
    for (int i = 1; i < C_; i++) {
        ull acc = 0ULL;
        #pragma unroll
        for (int j = 0; j < C_; j++) {
            if (j < i) {
                float m = Wl[i*65 + j];
                acc = fma2(pk2(m, m), bvw[j], acc);
            }
        }
        bvw[i] = add2(bvw[i], acc ^ SGN2);
    }
    #pragma unroll
    for (int i = 0; i < C_; i++) {
        float2 f = upk2(bvw[i]);
        g_vcorr [(ib + i) * HD_ + c] = f.x;
        g_wkcorr[(ib + i) * HD_ + c] = f.y;
    }
}

// ---------------- chunk scan: 128 independent CTAs (bh x 16-col block) -------
#define SCAN_SMEM_BYTES 182288
__global__ __launch_bounds__(256) void scan_kernel() {
    extern __shared__ float sm[];
    float* S_s  = sm;
    float* wkc  = sm + 5120;
    float* rks  = sm + 21760;
    float* intr = sm + 38660;
    float* vco  = sm + 43012;
    float* vnw  = sm + 44292;
    __shared__ float gp_s[C_ + 1];
    __shared__ float s_alpha;

    const int tid = threadIdx.x;
    const int bh  = blockIdx.y;
    const int c0  = blockIdx.x * 16;
    const int b   = bh >> 2, h = bh & 3;

    if (tid <= C_) gp_s[tid] = g_gpow[h][tid];
    if (tid == 0) s_alpha = g_alpha[h];
    for (int q = tid; q < 256 * 20; q += 256) S_s[q] = 0.f;
    __syncthreads();

    const int iA = tid >> 2;            // 0..63 (row within chunk)
    const int cq = (tid & 3) << 2;      // 0,4,8,12 (col group)

    for (int n = 0; n < N_; n++) {
        size_t cb = ((size_t)(bh * N_ + n)) * C_;
        #pragma unroll
        for (int rr = 0; rr < 16; rr++) {
            int q = tid + (rr << 8);
            int i = q >> 6, k4 = (q & 63) << 2;
            *(float4*)&wkc[i*260 + k4] = *(const float4*)(g_wkcorr + (cb + i)*HD_ + k4);
        }
        #pragma unroll
        for (int rr = 0; rr < 17; rr++) {
            int q = tid + (rr << 8);
            if (q < 4160) {
                int i = q >> 6, k4 = (q & 63) << 2;
                int t = n*C_ - 1 + i;
                float4 v = (t >= 0) ? *(const float4*)(g_rk + ((size_t)bh*T_ + t)*HD_ + k4)
                                    : make_float4(0.f, 0.f, 0.f, 0.f);
                *(float4*)&rks[i*260 + k4] = v;
            }
        }
        #pragma unroll
        for (int rr = 0; rr < 4; rr++) {
            int q = tid + (rr << 8);
            int i = q >> 4, j4 = (q & 15) << 2;
            *(float4*)&intr[i*68 + j4] = *(const float4*)(g_intra + (cb + i)*C_ + j4);
        }
        {
            int i = tid >> 2;
            *(float4*)&vco[i*20 + cq] = *(const float4*)(g_vcorr + (cb + i)*HD_ + c0 + cq);
        }
        __syncthreads();

        // ---- (A) t1 = wkc @ S, orr = rk @ S ; v_new = vco - t1 ----
        ull t1a = 0, t1b = 0, oa = 0, ob = 0;
        {
            const float* wrow = wkc + iA*260;
            const float* rrow = rks + (iA + 1)*260;
            #pragma unroll 4
            for (int k = 0; k < HD_; k += 4) {
                float4 w4 = *(const float4*)(wrow + k);
                float4 r4 = *(const float4*)(rrow + k);
                float wl[4] = {w4.x, w4.y, w4.z, w4.w};
                float rl[4] = {r4.x, r4.y, r4.z, r4.w};
                #pragma unroll
                for (int u = 0; u < 4; u++) {
                    ulonglong2 s = *(const ulonglong2*)&S_s[(k + u)*20 + cq];
                    ull w2 = pk2(wl[u], wl[u]);
                    ull r2 = pk2(rl[u], rl[u]);
                    t1a = fma2(w2, s.x, t1a);
                    t1b = fma2(w2, s.y, t1b);
                    oa  = fma2(r2, s.x, oa);
                    ob  = fma2(r2, s.y, ob);
                }
            }
            ulonglong2 vc2 = *(const ulonglong2*)&vco[iA*20 + cq];
            ulonglong2 vn2;
            vn2.x = add2(vc2.x, t1a ^ SGN2);
            vn2.y = add2(vc2.y, t1b ^ SGN2);
            *(ulonglong2*)&vnw[iA*20 + cq] = vn2;
        }
        __syncthreads();

        // ---- (C) o = gamma^i * orr + intra @ v_new ; write alpha*o ----
        {
            float gi = gp_s[iA];
            ull gi2 = pk2(gi, gi);
            oa = mul2(oa, gi2); ob = mul2(ob, gi2);
            const float* irow = intr + iA*68;
            #pragma unroll 8
            for (int j = 0; j < C_; j++) {
                float m = irow[j];
                ull m2 = pk2(m, m);
                ulonglong2 vn = *(const ulonglong2*)&vnw[j*20 + cq];
                oa = fma2(m2, vn.x, oa);
                ob = fma2(m2, vn.y, ob);
            }
            ull al2 = pk2(s_alpha, s_alpha);
            oa = mul2(oa, al2); ob = mul2(ob, al2);
            float2 p0 = upk2(oa), p1 = upk2(ob);
            *(float4*)(g_o + ((size_t)b*T_ + n*C_ + iA)*D_ + h*HD_ + c0 + cq)
                = make_float4(p0.x, p0.y, p1.x, p1.y);
        }
        __syncthreads();

        // ---- (D) S = gamma^C * S + wk_g^T @ v_new ----
        {
            float gC = gp_s[C_];
            ull gc2 = pk2(gC, gC);
            ull s8[8];
            #pragma unroll
            for (int q = 0; q < 4; q++) {
                ulonglong2 t = *(const ulonglong2*)&S_s[tid*20 + q*4];
                s8[2*q]   = mul2(t.x, gc2);
                s8[2*q+1] = mul2(t.y, gc2);
            }
            #pragma unroll 4
            for (int j = 0; j < C_; j++) {
                float w = rks[j*260 + tid] * gp_s[63 - j];
                ull w2 = pk2(w, w);
                #pragma unroll
                for (int q = 0; q < 4; q++) {
                    ulonglong2 vn = *(const ulonglong2*)&vnw[j*20 + q*4];
                    s8[2*q]   = fma2(w2, vn.x, s8[2*q]);
                    s8[2*q+1] = fma2(w2, vn.y, s8[2*q+1]);
                }
            }
            #pragma unroll
            for (int q = 0; q < 4; q++) {
                ulonglong2 t;
                t.x = s8[2*q]; t.y = s8[2*q+1];
                *(ulonglong2*)&S_s[tid*20 + q*4] = t;
            }
        }
        __syncthreads();
    }
}

// ---------------- launch ----------------
extern "C" void kernel_launch(void* const* d_in, const int* in_sizes, int n_in,
                              void* d_out, int out_size) {
    const float* x     = (const float*)d_in[0];
    const float* Ww    = (const float*)d_in[1];
    const float* Wr    = (const float*)d_in[2];
    const float* decay = (const float*)d_in[3];
    const float* lalp  = (const float*)d_in[4];
    float* out = (float*)d_out;

    cudaFuncSetAttribute(scan_kernel, cudaFuncAttributeMaxDynamicSharedMemorySize,
                         SCAN_SMEM_BYTES);

    void *pv = nullptr, *po = nullptr, *pxb = nullptr, *pob = nullptr;
    void *pwwb = nullptr, *pwrb = nullptr;
    cudaGetSymbolAddress(&pv, g_v);
    cudaGetSymbolAddress(&po, g_o);
    cudaGetSymbolAddress(&pxb, g_xb);
    cudaGetSymbolAddress(&pob, g_ob);
    cudaGetSymbolAddress(&pwwb, g_Wwb);
    cudaGetSymbolAddress(&pwrb, g_Wrb);

    const size_t ND = (size_t)B_ * T_ * D_;   // 16,777,216
    const size_t NW = (size_t)D_ * D_;        // 1,048,576

    setup_kernel<<<1, 32>>>(decay, lalp);
    rk_kernel<<<(B_ * T_ * H_) / 8, 256>>>(x);
    conv_bf16<<<(int)(ND / 2048), 256>>>(x,  (__nv_bfloat16*)pxb);
    conv_bf16<<<(int)(NW / 2048), 256>>>(Ww, (__nv_bfloat16*)pwwb);
    conv_bf16<<<(int)(NW / 2048), 256>>>(Wr, (__nv_bfloat16*)pwrb);
    gemm_bf16_tn<<<dim3(D_ / 128, (B_ * T_) / 128), 256>>>(
        (const __nv_bfloat16*)pxb, (const __nv_bfloat16*)pwwb, nullptr, (float*)pv);
    prep_kernel<<<BH_ * N_, 256>>>();
    scan_kernel<<<dim3(16, BH_), 256, SCAN_SMEM_BYTES>>>();
    conv_bf16<<<(int)(ND / 2048), 256>>>((const float*)po, (__nv_bfloat16*)pob);
    gemm_bf16_tn<<<dim3(D_ / 128, (B_ * T_) / 128), 256>>>(
        (const __nv_bfloat16*)pob, (const __nv_bfloat16*)pwrb, x, out);
}

// round 6
// speedup vs baseline: 1.9481x; 1.9481x over previous
#include <cuda_runtime.h>
#include <cuda_bf16.h>

#define B_    2
#define T_    8192
#define D_    1024
#define H_    4
#define HD_   256
#define C_    64
#define N_    128
#define BH_   8

typedef unsigned long long ull;

__device__ __forceinline__ ull pk2(float a, float b) {
    ull r; asm("mov.b64 %0, {%1, %2};" : "=l"(r) : "f"(a), "f"(b)); return r;
}
__device__ __forceinline__ float2 upk2(ull v) {
    float2 f; asm("mov.b64 {%0, %1}, %2;" : "=f"(f.x), "=f"(f.y) : "l"(v)); return f;
}
__device__ __forceinline__ ull fma2(ull a, ull b, ull c) {
    ull d; asm("fma.rn.f32x2 %0, %1, %2, %3;" : "=l"(d) : "l"(a), "l"(b), "l"(c)); return d;
}
__device__ __forceinline__ ull add2(ull a, ull b) {
    ull d; asm("add.rn.f32x2 %0, %1, %2;" : "=l"(d) : "l"(a), "l"(b)); return d;
}
#define SGN2 0x8000000080000000ULL

__device__ __forceinline__ unsigned smem_u32(const void* p) {
    unsigned a;
    asm("{ .reg .u64 t; cvta.to.shared.u64 t, %1; cvt.u32.u64 %0, t; }" : "=r"(a) : "l"(p));
    return a;
}
#define LDSM4(r, addr) \
    asm volatile("ldmatrix.sync.aligned.m8n8.x4.shared.b16 {%0,%1,%2,%3}, [%4];" \
        : "=r"((r)[0]), "=r"((r)[1]), "=r"((r)[2]), "=r"((r)[3]) : "r"(addr))
#define MMA16816(d, a, b0v, b1v) \
    asm volatile("mma.sync.aligned.m16n8k16.row.col.f32.bf16.bf16.f32 " \
        "{%0,%1,%2,%3}, {%4,%5,%6,%7}, {%8,%9}, {%0,%1,%2,%3};" \
        : "+f"((d)[0]), "+f"((d)[1]), "+f"((d)[2]), "+f"((d)[3]) \
        : "r"((a)[0]), "r"((a)[1]), "r"((a)[2]), "r"((a)[3]), "r"(b0v), "r"(b1v))
#define CPA16(dst, src) \
    asm volatile("cp.async.cg.shared.global [%0], [%1], 16;" :: "r"(dst), "l"(src))
#define CPCOMMIT() asm volatile("cp.async.commit_group;")
#define CPWAIT1()  asm volatile("cp.async.wait_group 1;")

// ---------------- device scratch ----------------
__device__ float g_v[(size_t)B_ * T_ * D_];
__device__ float g_rk[(size_t)BH_ * T_ * HD_];
__device__ float g_vcorr[(size_t)BH_ * N_ * C_ * HD_];
__device__ float g_gpow[H_][C_ + 1];
__device__ float g_alpha[H_];
__device__ __nv_bfloat16 g_xb [(size_t)B_ * T_ * D_];
__device__ __nv_bfloat16 g_ob [(size_t)B_ * T_ * D_];
__device__ __nv_bfloat16 g_Wwb[(size_t)D_ * D_];
__device__ __nv_bfloat16 g_Wrb[(size_t)D_ * D_];
__device__ __nv_bfloat16 g_rkb   [(size_t)BH_ * T_ * HD_];
__device__ __nv_bfloat16 g_wkcA_b[(size_t)BH_ * N_ * C_ * HD_];   // bf16(A@wk) [i][k]
__device__ __nv_bfloat16 g_intra_b[(size_t)BH_ * N_ * C_ * C_];   // [i][j]
__device__ __nv_bfloat16 g_wkgT  [(size_t)BH_ * N_ * HD_ * C_];   // [ks][j]

__global__ void setup_kernel(const float* __restrict__ decay,
                             const float* __restrict__ log_alpha) {
    int h = threadIdx.x;
    if (h < H_) {
        float g = 1.f / (1.f + expf(-decay[h]));
        g_alpha[h] = expf(log_alpha[h]);
        float p = 1.f;
        for (int i = 0; i <= C_; i++) { g_gpow[h][i] = p; p *= g; }
    }
}

__global__ __launch_bounds__(256) void conv_bf16(const float* __restrict__ in,
                                                 __nv_bfloat16* __restrict__ out) {
    size_t i = ((size_t)blockIdx.x * 256 + threadIdx.x) * 8;
    float4 a = *(const float4*)(in + i);
    float4 b = *(const float4*)(in + i + 4);
    __nv_bfloat162 r0 = __floats2bfloat162_rn(a.x, a.y);
    __nv_bfloat162 r1 = __floats2bfloat162_rn(a.z, a.w);
    __nv_bfloat162 r2 = __floats2bfloat162_rn(b.x, b.y);
    __nv_bfloat162 r3 = __floats2bfloat162_rn(b.z, b.w);
    uint4 pk;
    pk.x = *(unsigned*)&r0; pk.y = *(unsigned*)&r1;
    pk.z = *(unsigned*)&r2; pk.w = *(unsigned*)&r3;
    *(uint4*)(out + i) = pk;
}

__global__ __launch_bounds__(256) void rk_kernel(const float* __restrict__ x) {
    int warp = threadIdx.x >> 5, lane = threadIdx.x & 31;
    int row = blockIdx.x * 8 + warp;
    int h  = row & (H_ - 1);
    int bt = row >> 2;
    const float* xp = x + (size_t)bt * D_ + h * HD_ + lane * 8;
    float4 v0 = *(const float4*)(xp);
    float4 v1 = *(const float4*)(xp + 4);
    float ss = v0.x*v0.x + v0.y*v0.y + v0.z*v0.z + v0.w*v0.w
             + v1.x*v1.x + v1.y*v1.y + v1.z*v1.z + v1.w*v1.w;
    #pragma unroll
    for (int o = 16; o; o >>= 1) ss += __shfl_xor_sync(0xffffffffu, ss, o);
    float inv = 1.f / fmaxf(sqrtf(ss), 1e-12f);
    int b = bt >> 13, t = bt & (T_ - 1);
    size_t base = ((size_t)(b * H_ + h) * T_ + t) * HD_ + lane * 8;
    float4 o0 = make_float4(v0.x*inv, v0.y*inv, v0.z*inv, v0.w*inv);
    float4 o1 = make_float4(v1.x*inv, v1.y*inv, v1.z*inv, v1.w*inv);
    *(float4*)(g_rk + base)     = o0;
    *(float4*)(g_rk + base + 4) = o1;
    __nv_bfloat162 q0 = __floats2bfloat162_rn(o0.x, o0.y);
    __nv_bfloat162 q1 = __floats2bfloat162_rn(o0.z, o0.w);
    __nv_bfloat162 q2 = __floats2bfloat162_rn(o1.x, o1.y);
    __nv_bfloat162 q3 = __floats2bfloat162_rn(o1.z, o1.w);
    uint4 pk;
    pk.x = *(unsigned*)&q0; pk.y = *(unsigned*)&q1;
    pk.z = *(unsigned*)&q2; pk.w = *(unsigned*)&q3;
    *(uint4*)(g_rkb + base) = pk;
}

// ---------------- bf16 tensor-core GEMM (TN) ----------------
#define RSE 40
__global__ __launch_bounds__(256) void gemm_bf16_tn(const __nv_bfloat16* __restrict__ A,
                                                    const __nv_bfloat16* __restrict__ W,
                                                    const float* __restrict__ Cin,
                                                    float* __restrict__ Cout) {
    __shared__ __nv_bfloat16 As[128 * RSE];
    __shared__ __nv_bfloat16 Bs[128 * RSE];
    const int tid = threadIdx.x;
    const int bm = blockIdx.y * 128, bn = blockIdx.x * 128;
    const int wid = tid >> 5, lane = tid & 31;
    const int wm = (wid & 3) * 32, wn = (wid >> 2) * 64;
    const int lr = tid >> 2, lk = (tid & 3) * 8;
    const __nv_bfloat16* Ap0 = A + (size_t)(bm + lr) * D_ + lk;
    const __nv_bfloat16* Ap1 = A + (size_t)(bm + lr + 64) * D_ + lk;
    const __nv_bfloat16* Wp0 = W + (size_t)(bn + lr) * D_ + lk;
    const __nv_bfloat16* Wp1 = W + (size_t)(bn + lr + 64) * D_ + lk;
    const unsigned a_base = smem_u32(As) +
        (unsigned)((wm + (lane & 7) + ((lane >> 3) & 1) * 8) * (RSE * 2) + (lane >> 4) * 16);
    const unsigned b_base = smem_u32(Bs) +
        (unsigned)((wn + (lane & 7) + ((lane >> 4) & 1) * 8) * (RSE * 2) + ((lane >> 3) & 1) * 16);
    float acc[2][8][4];
    #pragma unroll
    for (int mt = 0; mt < 2; mt++)
        #pragma unroll
        for (int nt = 0; nt < 8; nt++)
            #pragma unroll
            for (int q = 0; q < 4; q++) acc[mt][nt][q] = 0.f;
    uint4 pa0 = *(const uint4*)(Ap0), pa1 = *(const uint4*)(Ap1);
    uint4 pb0 = *(const uint4*)(Wp0), pb1 = *(const uint4*)(Wp1);
    for (int k0 = 0; k0 < D_; k0 += 32) {
        __syncthreads();
        *(uint4*)&As[lr * RSE + lk]        = pa0;
        *(uint4*)&As[(lr + 64) * RSE + lk] = pa1;
        *(uint4*)&Bs[lr * RSE + lk]        = pb0;
        *(uint4*)&Bs[(lr + 64) * RSE + lk] = pb1;
        __syncthreads();
        if (k0 + 32 < D_) {
            pa0 = *(const uint4*)(Ap0 + k0 + 32);
            pa1 = *(const uint4*)(Ap1 + k0 + 32);
            pb0 = *(const uint4*)(Wp0 + k0 + 32);
            pb1 = *(const uint4*)(Wp1 + k0 + 32);
        }
        #pragma unroll
        for (int kk = 0; kk < 2; kk++) {
            unsigned ka = a_base + kk * 32, kb = b_base + kk * 32;
            unsigned af[2][4], bf[4][4];
            #pragma unroll
            for (int mt = 0; mt < 2; mt++) LDSM4(af[mt], ka + mt * 16 * (RSE * 2));
            #pragma unroll
            for (int j = 0; j < 4; j++) LDSM4(bf[j], kb + j * 16 * (RSE * 2));
            #pragma unroll
            for (int mt = 0; mt < 2; mt++)
                #pragma unroll
                for (int nt = 0; nt < 8; nt++)
                    MMA16816(acc[mt][nt], af[mt],
                             bf[nt >> 1][(nt & 1) * 2 + 0], bf[nt >> 1][(nt & 1) * 2 + 1]);
        }
    }
    const int rr = lane >> 2, cc = (lane & 3) * 2;
    #pragma unroll
    for (int mt = 0; mt < 2; mt++) {
        int row = bm + wm + mt * 16 + rr;
        #pragma unroll
        for (int nt = 0; nt < 8; nt++) {
            int col = bn + wn + nt * 8 + cc;
            float2 lo = make_float2(acc[mt][nt][0], acc[mt][nt][1]);
            float2 hi = make_float2(acc[mt][nt][2], acc[mt][nt][3]);
            if (Cin) {
                float2 c0 = *(const float2*)(Cin + (size_t)row * D_ + col);
                float2 c1 = *(const float2*)(Cin + (size_t)(row + 8) * D_ + col);
                lo.x += c0.x; lo.y += c0.y; hi.x += c1.x; hi.y += c1.y;
            }
            *(float2*)(Cout + (size_t)row * D_ + col)       = lo;
            *(float2*)(Cout + (size_t)(row + 8) * D_ + col) = hi;
        }
    }
}

// ---------------- chunk prep ----------------
__global__ __launch_bounds__(256) void prep_kernel() {
    __shared__ float wkT[16 * 68];
    __shared__ float rkT[16 * 68];
    __shared__ float Wl[64 * 65];
    __shared__ float gp_s[C_ + 1];
    const int tid = threadIdx.x;
    const int n  = blockIdx.x & (N_ - 1);
    const int bh = blockIdx.x >> 7;
    const int b  = bh >> 2, h = bh & 3;
    const int tx = tid & 15, ty = tid >> 4;
    if (tid <= C_) gp_s[tid] = g_gpow[h][tid];
    ull accW[4][2], accR[4][2];
    #pragma unroll
    for (int a = 0; a < 4; a++) { accW[a][0]=0; accW[a][1]=0; accR[a][0]=0; accR[a][1]=0; }
    for (int ks = 0; ks < 16; ks++) {
        int k0 = ks * 16;
        __syncthreads();
        #pragma unroll
        for (int e = 0; e < 4; e++) {
            int q = tid + e * 256;
            int kk = q & 15, j = q >> 4;
            rkT[kk*68 + j] = g_rk[((size_t)bh*T_ + n*C_ + j) * HD_ + k0 + kk];
            int tw = n*C_ + j - 1;
            wkT[kk*68 + j] = (tw >= 0)
                ? g_rk[((size_t)bh*T_ + tw) * HD_ + k0 + kk] : 0.f;
        }
        __syncthreads();
        #pragma unroll
        for (int kk = 0; kk < 16; kk++) {
            float4 wa = *(const float4*)&wkT[kk*68 + ty*4];
            float4 ra = *(const float4*)&rkT[kk*68 + ty*4];
            ulonglong2 wb = *(const ulonglong2*)&wkT[kk*68 + tx*4];
            ull wa2[4] = {pk2(wa.x,wa.x), pk2(wa.y,wa.y), pk2(wa.z,wa.z), pk2(wa.w,wa.w)};
            ull ra2[4] = {pk2(ra.x,ra.x), pk2(ra.y,ra.y), pk2(ra.z,ra.z), pk2(ra.w,ra.w)};
            #pragma unroll
            for (int a = 0; a < 4; a++) {
                accW[a][0] = fma2(wa2[a], wb.x, accW[a][0]);
                accW[a][1] = fma2(wa2[a], wb.y, accW[a][1]);
                accR[a][0] = fma2(ra2[a], wb.x, accR[a][0]);
                accR[a][1] = fma2(ra2[a], wb.y, accR[a][1]);
            }
        }
    }
    size_t ib = ((size_t)(bh * N_ + n)) * C_;
    #pragma unroll
    for (int a = 0; a < 4; a++) {
        int i = ty*4 + a;
        float2 w0 = upk2(accW[a][0]), w1 = upk2(accW[a][1]);
        float2 r0 = upk2(accR[a][0]), r1 = upk2(accR[a][1]);
        float wv[4] = {w0.x, w0.y, w1.x, w1.y};
        float rv[4] = {r0.x, r0.y, r1.x, r1.y};
        #pragma unroll
        for (int q = 0; q < 4; q++) {
            int j = tx*4 + q;
            float lg = (j < i) ? gp_s[i - j] : 0.f;
            Wl[i*65 + j] = wv[q] * lg;
            g_intra_b[(ib + i) * C_ + j] = __float2bfloat16(rv[q] * lg);
        }
    }
    __syncthreads();
    // forward substitution (v, wk) + wkg^T emit
    const int c = tid;
    ull bvw[C_];
    const size_t wgbase = ((size_t)(bh*N_ + n) * HD_ + c) * C_;
    #pragma unroll
    for (int i2 = 0; i2 < C_/2; i2++) {
        int i = 2*i2;
        float bv0 = g_v[((size_t)b*T_ + n*C_ + i) * D_ + h*HD_ + c];
        float bv1 = g_v[((size_t)b*T_ + n*C_ + i + 1) * D_ + h*HD_ + c];
        int tw0 = n*C_ + i - 1;
        float bw0 = (tw0 >= 0) ? g_rk[((size_t)bh*T_ + tw0) * HD_ + c] : 0.f;
        float bw1 = g_rk[((size_t)bh*T_ + tw0 + 1) * HD_ + c];
        bvw[i]   = pk2(bv0, bw0);
        bvw[i+1] = pk2(bv1, bw1);
        __nv_bfloat162 wp;
        wp.x = __float2bfloat16(bw0 * gp_s[63 - i]);
        wp.y = __float2bfloat16(bw1 * gp_s[62 - i]);
        *(__nv_bfloat162*)&g_wkgT[wgbase + i] = wp;
    }
    #pragma unroll
    for (int i = 1; i < C_; i++) {
        ull acc = 0ULL;
        #pragma unroll
        for (int j = 0; j < C_; j++) {
            if (j < i) {
                float m = Wl[i*65 + j];
                acc = fma2(pk2(m, m), bvw[j], acc);
            }
        }
        bvw[i] = add2(bvw[i], acc ^ SGN2);
    }
    #pragma unroll
    for (int i = 0; i < C_; i++) {
        float2 f = upk2(bvw[i]);
        g_vcorr [(ib + i) * HD_ + c] = f.x;
        g_wkcA_b[(ib + i) * HD_ + c] = __float2bfloat16(f.y);
    }
}

// ---------------- MMA chunk scan: 64 CTAs (8 bh x 8 col-slabs of 32) --------
#define AST_OFF 0
#define AST_BUF 67584
#define WGT_OFF 135168
#define SB_OFF  172032
#define VNT_OFF 188928
#define INT_OFF 193536
#define VCO_OFF 202752
#define GP_OFF  211968
#define SCAN_SMEM 212480

__global__ void __launch_bounds__(256, 1) scan_mma_kernel() {
    extern __shared__ char smc[];
    const unsigned sb = smem_u32(smc);
    const int tid = threadIdx.x, wid = tid >> 5, lane = tid & 31;
    const int bh = blockIdx.y, c0 = blockIdx.x * 32;
    const int b = bh >> 2, h = bh & 3;
    float* gps = (float*)(smc + GP_OFF);
    if (tid <= C_) gps[tid] = g_gpow[h][tid];
    if (tid == C_ + 1) gps[C_ + 1] = g_alpha[h];

    const __nv_bfloat16* gWkc = g_wkcA_b + (size_t)bh * N_ * C_ * HD_;
    const __nv_bfloat16* gRk  = g_rkb    + (size_t)bh * T_ * HD_;
    const __nv_bfloat16* gWg  = g_wkgT   + (size_t)bh * N_ * HD_ * C_;
    const __nv_bfloat16* gIn  = g_intra_b+ (size_t)bh * N_ * C_ * C_;
    const float*         gVc  = g_vcorr  + (size_t)bh * N_ * C_ * HD_;

    auto copyG1 = [&](int n) {
        int r = tid >> 1, half = tid & 1;
        unsigned d = sb + AST_OFF + (n & 1) * AST_BUF + r * 528 + half * 256;
        const __nv_bfloat16* s = (r < 64)
            ? gWkc + ((size_t)n * C_ + r) * HD_ + half * 128
            : gRk  + ((size_t)n * C_ + (r - 64)) * HD_ + half * 128;
        #pragma unroll
        for (int q = 0; q < 16; q++) CPA16(d + q * 16, s + q * 8);
    };
    auto copyG2 = [&](int n) {
        unsigned d1 = sb + WGT_OFF + tid * 144;
        const __nv_bfloat16* s1 = gWg + ((size_t)n * HD_ + tid) * C_;
        #pragma unroll
        for (int q = 0; q < 8; q++) CPA16(d1 + q * 16, s1 + q * 8);
        int row = tid >> 2, ch = tid & 3;
        unsigned d2 = sb + INT_OFF + row * 144 + ch * 32;
        const __nv_bfloat16* s2 = gIn + ((size_t)n * C_ + row) * C_ + ch * 16;
        CPA16(d2, s2); CPA16(d2 + 16, s2 + 8);
        unsigned d3 = sb + VCO_OFF + row * 144 + ch * 32;
        const float* s3 = gVc + ((size_t)n * C_ + row) * HD_ + c0 + ch * 8;
        CPA16(d3, s3); CPA16(d3 + 16, s3 + 4);
    };

    const unsigned aA = sb + AST_OFF + (wid * 16 + (lane & 15)) * 528 + (lane >> 4) * 16;
    const unsigned bS = sb + SB_OFF + ((lane & 7) + ((lane >> 4) & 1) * 8) * 528 + ((lane >> 3) & 1) * 16;
    const unsigned aV = sb + VNT_OFF + (lane & 15) * 144 + (lane >> 4) * 16;
    const unsigned bW = sb + WGT_OFF + (wid * 32 + (lane & 7) + ((lane >> 4) & 1) * 8) * 144 + ((lane >> 3) & 1) * 16;
    const unsigned aI = sb + INT_OFF + ((wid & 3) * 16 + (lane & 15)) * 144 + (lane >> 4) * 16;
    const unsigned bV = sb + VNT_OFF + ((lane & 7) + ((lane >> 4) & 1) * 8) * 144 + ((lane >> 3) & 1) * 16;

    float Sacc[2][4][4] = {};
    copyG1(0); CPCOMMIT();
    copyG2(0); CPCOMMIT();

    for (int n = 0; n < N_; n++) {
        // Sb = bf16(S^T) from accumulators
        #pragma unroll
        for (int ct = 0; ct < 2; ct++)
            #pragma unroll
            for (int nt = 0; nt < 4; nt++) {
                int c = ct * 16 + (lane >> 2);
                int ks = wid * 32 + nt * 8 + (lane & 3) * 2;
                *(__nv_bfloat162*)(smc + SB_OFF + c * 528 + ks * 2) =
                    __floats2bfloat162_rn(Sacc[ct][nt][0], Sacc[ct][nt][1]);
                *(__nv_bfloat162*)(smc + SB_OFF + (c + 8) * 528 + ks * 2) =
                    __floats2bfloat162_rn(Sacc[ct][nt][2], Sacc[ct][nt][3]);
            }
        if (n + 1 < N_) copyG1(n + 1);
        CPCOMMIT();
        CPWAIT1();
        __syncthreads();

        // phase A: [wkc;rk](128x256) @ S(256x32): warp rows 16*wid
        float accA[4][4] = {};
        {
            unsigned ab = aA + (n & 1) * AST_BUF;
            #pragma unroll
            for (int k = 0; k < 16; k++) {
                unsigned af[4], b0[4], b1[4];
                LDSM4(af, ab + k * 32);
                LDSM4(b0, bS + k * 32);
                LDSM4(b1, bS + 8448 + k * 32);
                MMA16816(accA[0], af, b0[0], b0[1]);
                MMA16816(accA[1], af, b0[2], b0[3]);
                MMA16816(accA[2], af, b1[0], b1[1]);
                MMA16816(accA[3], af, b1[2], b1[3]);
            }
        }
        int r0 = (wid & 3) * 16 + (lane >> 2);
        if (wid < 4) {   // v_new = vco - t1, write v_new^T bf16
            #pragma unroll
            for (int nt = 0; nt < 4; nt++) {
                int cc = nt * 8 + (lane & 3) * 2;
                float2 v0 = *(float2*)(smc + VCO_OFF + r0 * 144 + cc * 4);
                float2 v1 = *(float2*)(smc + VCO_OFF + (r0 + 8) * 144 + cc * 4);
                *(__nv_bfloat16*)(smc + VNT_OFF + cc * 144 + r0 * 2)       = __float2bfloat16(v0.x - accA[nt][0]);
                *(__nv_bfloat16*)(smc + VNT_OFF + (cc + 1) * 144 + r0 * 2) = __float2bfloat16(v0.y - accA[nt][1]);
                *(__nv_bfloat16*)(smc + VNT_OFF + cc * 144 + (r0 + 8) * 2)       = __float2bfloat16(v1.x - accA[nt][2]);
                *(__nv_bfloat16*)(smc + VNT_OFF + (cc + 1) * 144 + (r0 + 8) * 2) = __float2bfloat16(v1.y - accA[nt][3]);
            }
        } else {         // orr *= gamma^i
            float g0 = gps[r0], g1 = gps[r0 + 8];
            #pragma unroll
            for (int nt = 0; nt < 4; nt++) {
                accA[nt][0] *= g0; accA[nt][1] *= g0;
                accA[nt][2] *= g1; accA[nt][3] *= g1;
            }
        }
        __syncthreads();

        // phase C (warps 4-7): o = orr*g + intra @ v_new; write alpha*o bf16
        if (wid >= 4) {
            #pragma unroll
            for (int k = 0; k < 4; k++) {
                unsigned ai[4], v0[4], v1[4];
                LDSM4(ai, aI + k * 32);
                LDSM4(v0, bV + k * 32);
                LDSM4(v1, bV + 2304 + k * 32);
                MMA16816(accA[0], ai, v0[0], v0[1]);
                MMA16816(accA[1], ai, v0[2], v0[3]);
                MMA16816(accA[2], ai, v1[0], v1[1]);
                MMA16816(accA[3], ai, v1[2], v1[3]);
            }
            float al = gps[C_ + 1];
            size_t ob = ((size_t)b * T_ + n * C_) * D_ + h * HD_ + c0;
            #pragma unroll
            for (int nt = 0; nt < 4; nt++) {
                int cc = nt * 8 + (lane & 3) * 2;
                *(__nv_bfloat162*)(g_ob + ob + (size_t)r0 * D_ + cc) =
                    __floats2bfloat162_rn(accA[nt][0] * al, accA[nt][1] * al);
                *(__nv_bfloat162*)(g_ob + ob + (size_t)(r0 + 8) * D_ + cc) =
                    __floats2bfloat162_rn(accA[nt][2] * al, accA[nt][3] * al);
            }
        }

        // phase D: S^T = gC*S^T + v_new^T @ wkg (all warps)
        {
            float gC = gps[C_];
            #pragma unroll
            for (int ct = 0; ct < 2; ct++)
                #pragma unroll
                for (int nt = 0; nt < 4; nt++)
                    #pragma unroll
                    for (int q = 0; q < 4; q++) Sacc[ct][nt][q] *= gC;
            #pragma unroll
            for (int k = 0; k < 4; k++) {
                unsigned a0[4], a1[4], w0[4], w1[4];
                LDSM4(a0, aV + k * 32);
                LDSM4(a1, aV + 2304 + k * 32);
                LDSM4(w0, bW + k * 32);
                LDSM4(w1, bW + 2304 + k * 32);
                MMA16816(Sacc[0][0], a0, w0[0], w0[1]);
                MMA16816(Sacc[0][1], a0, w0[2], w0[3]);
                MMA16816(Sacc[0][2], a0, w1[0], w1[1]);
                MMA16816(Sacc[0][3], a0, w1[2], w1[3]);
                MMA16816(Sacc[1][0], a1, w0[0], w0[1]);
                MMA16816(Sacc[1][1], a1, w0[2], w0[3]);
                MMA16816(Sacc[1][2], a1, w1[0], w1[1]);
                MMA16816(Sacc[1][3], a1, w1[2], w1[3]);
            }
        }
        __syncthreads();
        if (n + 1 < N_) copyG2(n + 1);
        CPCOMMIT();
    }
}

// ---------------- launch ----------------
extern "C" void kernel_launch(void* const* d_in, const int* in_sizes, int n_in,
                              void* d_out, int out_size) {
    const float* x     = (const float*)d_in[0];
    const float* Ww    = (const float*)d_in[1];
    const float* Wr    = (const float*)d_in[2];
    const float* decay = (const float*)d_in[3];
    const float* lalp  = (const float*)d_in[4];
    float* out = (float*)d_out;

    cudaFuncSetAttribute(scan_mma_kernel, cudaFuncAttributeMaxDynamicSharedMemorySize,
                         SCAN_SMEM);

    void *pv = nullptr, *pxb = nullptr, *pob = nullptr, *pwwb = nullptr, *pwrb = nullptr;
    cudaGetSymbolAddress(&pv, g_v);
    cudaGetSymbolAddress(&pxb, g_xb);
    cudaGetSymbolAddress(&pob, g_ob);
    cudaGetSymbolAddress(&pwwb, g_Wwb);
    cudaGetSymbolAddress(&pwrb, g_Wrb);

    const size_t ND = (size_t)B_ * T_ * D_;
    const size_t NW = (size_t)D_ * D_;

    setup_kernel<<<1, 32>>>(decay, lalp);
    rk_kernel<<<(B_ * T_ * H_) / 8, 256>>>(x);
    conv_bf16<<<(int)(ND / 2048), 256>>>(x,  (__nv_bfloat16*)pxb);
    conv_bf16<<<(int)(NW / 2048), 256>>>(Ww, (__nv_bfloat16*)pwwb);
    conv_bf16<<<(int)(NW / 2048), 256>>>(Wr, (__nv_bfloat16*)pwrb);
    gemm_bf16_tn<<<dim3(D_ / 128, (B_ * T_) / 128), 256>>>(
        (const __nv_bfloat16*)pxb, (const __nv_bfloat16*)pwwb, nullptr, (float*)pv);
    prep_kernel<<<BH_ * N_, 256>>>();
    scan_mma_kernel<<<dim3(8, BH_), 256, SCAN_SMEM>>>();
    gemm_bf16_tn<<<dim3(D_ / 128, (B_ * T_) / 128), 256>>>(
        (const __nv_bfloat16*)pob, (const __nv_bfloat16*)pwrb, x, out);
}

// round 9
// speedup vs baseline: 2.0701x; 1.0627x over previous
#include <cuda_runtime.h>
#include <cuda_bf16.h>

#define B_    2
#define T_    8192
#define D_    1024
#define H_    4
#define HD_   256
#define C_    64
#define N_    128
#define BH_   8

typedef unsigned long long ull;

__device__ __forceinline__ ull pk2(float a, float b) {
    ull r; asm("mov.b64 %0, {%1, %2};" : "=l"(r) : "f"(a), "f"(b)); return r;
}
__device__ __forceinline__ float2 upk2(ull v) {
    float2 f; asm("mov.b64 {%0, %1}, %2;" : "=f"(f.x), "=f"(f.y) : "l"(v)); return f;
}
__device__ __forceinline__ ull fma2(ull a, ull b, ull c) {
    ull d; asm("fma.rn.f32x2 %0, %1, %2, %3;" : "=l"(d) : "l"(a), "l"(b), "l"(c)); return d;
}
__device__ __forceinline__ ull add2(ull a, ull b) {
    ull d; asm("add.rn.f32x2 %0, %1, %2;" : "=l"(d) : "l"(a), "l"(b)); return d;
}
#define SGN2 0x8000000080000000ULL

__device__ __forceinline__ unsigned smem_u32(const void* p) {
    unsigned a;
    asm("{ .reg .u64 t; cvta.to.shared.u64 t, %1; cvt.u32.u64 %0, t; }" : "=r"(a) : "l"(p));
    return a;
}
#define LDSM4(r, addr) \
    asm volatile("ldmatrix.sync.aligned.m8n8.x4.shared.b16 {%0,%1,%2,%3}, [%4];" \
        : "=r"((r)[0]), "=r"((r)[1]), "=r"((r)[2]), "=r"((r)[3]) : "r"(addr))
#define MMA16816(d, a, b0v, b1v) \
    asm volatile("mma.sync.aligned.m16n8k16.row.col.f32.bf16.bf16.f32 " \
        "{%0,%1,%2,%3}, {%4,%5,%6,%7}, {%8,%9}, {%0,%1,%2,%3};" \
        : "+f"((d)[0]), "+f"((d)[1]), "+f"((d)[2]), "+f"((d)[3]) \
        : "r"((a)[0]), "r"((a)[1]), "r"((a)[2]), "r"((a)[3]), "r"(b0v), "r"(b1v))
#define CPA16(dst, src) \
    asm volatile("cp.async.cg.shared.global [%0], [%1], 16;" :: "r"(dst), "l"(src))
#define CPCOMMIT() asm volatile("cp.async.commit_group;")
#define CPWAIT1()  asm volatile("cp.async.wait_group 1;")
#define CPWAIT0()  asm volatile("cp.async.wait_group 0;")

// ---------------- device scratch ----------------
__device__ float g_v[(size_t)B_ * T_ * D_];
__device__ float g_rk[(size_t)BH_ * T_ * HD_];
__device__ float g_vcorr[(size_t)BH_ * N_ * C_ * HD_];
__device__ float g_gpow[H_][C_ + 1];
__device__ float g_alpha[H_];
__device__ __nv_bfloat16 g_xb [(size_t)B_ * T_ * D_];
__device__ __nv_bfloat16 g_ob [(size_t)B_ * T_ * D_];
__device__ __nv_bfloat16 g_Wwb[(size_t)D_ * D_];
__device__ __nv_bfloat16 g_Wrb[(size_t)D_ * D_];
__device__ __nv_bfloat16 g_rkb   [(size_t)BH_ * T_ * HD_];
__device__ __nv_bfloat16 g_wkcA_b[(size_t)BH_ * N_ * C_ * HD_];
__device__ __nv_bfloat16 g_intra_b[(size_t)BH_ * N_ * C_ * C_];
__device__ __nv_bfloat16 g_wkgT  [(size_t)BH_ * N_ * HD_ * C_];

__global__ void setup_kernel(const float* __restrict__ decay,
                             const float* __restrict__ log_alpha) {
    int h = threadIdx.x;
    if (h < H_) {
        float g = 1.f / (1.f + expf(-decay[h]));
        g_alpha[h] = expf(log_alpha[h]);
        float p = 1.f;
        for (int i = 0; i <= C_; i++) { g_gpow[h][i] = p; p *= g; }
    }
}

__global__ __launch_bounds__(256) void conv_bf16(const float* __restrict__ in,
                                                 __nv_bfloat16* __restrict__ out) {
    size_t i = ((size_t)blockIdx.x * 256 + threadIdx.x) * 8;
    float4 a = *(const float4*)(in + i);
    float4 b = *(const float4*)(in + i + 4);
    __nv_bfloat162 r0 = __floats2bfloat162_rn(a.x, a.y);
    __nv_bfloat162 r1 = __floats2bfloat162_rn(a.z, a.w);
    __nv_bfloat162 r2 = __floats2bfloat162_rn(b.x, b.y);
    __nv_bfloat162 r3 = __floats2bfloat162_rn(b.z, b.w);
    uint4 pk;
    pk.x = *(unsigned*)&r0; pk.y = *(unsigned*)&r1;
    pk.z = *(unsigned*)&r2; pk.w = *(unsigned*)&r3;
    *(uint4*)(out + i) = pk;
}

// rk normalize (writes f32 + bf16), fused x -> g_xb bf16
__global__ __launch_bounds__(256) void rk_kernel(const float* __restrict__ x) {
    int warp = threadIdx.x >> 5, lane = threadIdx.x & 31;
    int row = blockIdx.x * 8 + warp;
    int h  = row & (H_ - 1);
    int bt = row >> 2;
    const float* xp = x + (size_t)bt * D_ + h * HD_ + lane * 8;
    float4 v0 = *(const float4*)(xp);
    float4 v1 = *(const float4*)(xp + 4);
    // fused x -> bf16
    {
        __nv_bfloat162 q0 = __floats2bfloat162_rn(v0.x, v0.y);
        __nv_bfloat162 q1 = __floats2bfloat162_rn(v0.z, v0.w);
        __nv_bfloat162 q2 = __floats2bfloat162_rn(v1.x, v1.y);
        __nv_bfloat162 q3 = __floats2bfloat162_rn(v1.z, v1.w);
        uint4 pk;
        pk.x = *(unsigned*)&q0; pk.y = *(unsigned*)&q1;
        pk.z = *(unsigned*)&q2; pk.w = *(unsigned*)&q3;
        *(uint4*)(g_xb + (size_t)bt * D_ + h * HD_ + lane * 8) = pk;
    }
    float ss = v0.x*v0.x + v0.y*v0.y + v0.z*v0.z + v0.w*v0.w
             + v1.x*v1.x + v1.y*v1.y + v1.z*v1.z + v1.w*v1.w;
    #pragma unroll
    for (int o = 16; o; o >>= 1) ss += __shfl_xor_sync(0xffffffffu, ss, o);
    float inv = 1.f / fmaxf(sqrtf(ss), 1e-12f);
    int b = bt >> 13, t = bt & (T_ - 1);
    size_t base = ((size_t)(b * H_ + h) * T_ + t) * HD_ + lane * 8;
    float4 o0 = make_float4(v0.x*inv, v0.y*inv, v0.z*inv, v0.w*inv);
    float4 o1 = make_float4(v1.x*inv, v1.y*inv, v1.z*inv, v1.w*inv);
    *(float4*)(g_rk + base)     = o0;
    *(float4*)(g_rk + base + 4) = o1;
    __nv_bfloat162 q0 = __floats2bfloat162_rn(o0.x, o0.y);
    __nv_bfloat162 q1 = __floats2bfloat162_rn(o0.z, o0.w);
    __nv_bfloat162 q2 = __floats2bfloat162_rn(o1.x, o1.y);
    __nv_bfloat162 q3 = __floats2bfloat162_rn(o1.z, o1.w);
    uint4 pk;
    pk.x = *(unsigned*)&q0; pk.y = *(unsigned*)&q1;
    pk.z = *(unsigned*)&q2; pk.w = *(unsigned*)&q3;
    *(uint4*)(g_rkb + base) = pk;
}

// ---------------- bf16 tensor-core GEMM (TN) ----------------
#define RSE 40
__global__ __launch_bounds__(256) void gemm_bf16_tn(const __nv_bfloat16* __restrict__ A,
                                                    const __nv_bfloat16* __restrict__ W,
                                                    const float* __restrict__ Cin,
                                                    float* __restrict__ Cout) {
    __shared__ __nv_bfloat16 As[128 * RSE];
    __shared__ __nv_bfloat16 Bs[128 * RSE];
    const int tid = threadIdx.x;
    const int bm = blockIdx.y * 128, bn = blockIdx.x * 128;
    const int wid = tid >> 5, lane = tid & 31;
    const int wm = (wid & 3) * 32, wn = (wid >> 2) * 64;
    const int lr = tid >> 2, lk = (tid & 3) * 8;
    const __nv_bfloat16* Ap0 = A + (size_t)(bm + lr) * D_ + lk;
    const __nv_bfloat16* Ap1 = A + (size_t)(bm + lr + 64) * D_ + lk;
    const __nv_bfloat16* Wp0 = W + (size_t)(bn + lr) * D_ + lk;
    const __nv_bfloat16* Wp1 = W + (size_t)(bn + lr + 64) * D_ + lk;
    const unsigned a_base = smem_u32(As) +
        (unsigned)((wm + (lane & 7) + ((lane >> 3) & 1) * 8) * (RSE * 2) + (lane >> 4) * 16);
    const unsigned b_base = smem_u32(Bs) +
        (unsigned)((wn + (lane & 7) + ((lane >> 4) & 1) * 8) * (RSE * 2) + ((lane >> 3) & 1) * 16);
    float acc[2][8][4];
    #pragma unroll
    for (int mt = 0; mt < 2; mt++)
        #pragma unroll
        for (int nt = 0; nt < 8; nt++)
            #pragma unroll
            for (int q = 0; q < 4; q++) acc[mt][nt][q] = 0.f;
    uint4 pa0 = *(const uint4*)(Ap0), pa1 = *(const uint4*)(Ap1);
    uint4 pb0 = *(const uint4*)(Wp0), pb1 = *(const uint4*)(Wp1);
    for (int k0 = 0; k0 < D_; k0 += 32) {
        __syncthreads();
        *(uint4*)&As[lr * RSE + lk]        = pa0;
        *(uint4*)&As[(lr + 64) * RSE + lk] = pa1;
        *(uint4*)&Bs[lr * RSE + lk]        = pb0;
        *(uint4*)&Bs[(lr + 64) * RSE + lk] = pb1;
        __syncthreads();
        if (k0 + 32 < D_) {
            pa0 = *(const uint4*)(Ap0 + k0 + 32);
            pa1 = *(const uint4*)(Ap1 + k0 + 32);
            pb0 = *(const uint4*)(Wp0 + k0 + 32);
            pb1 = *(const uint4*)(Wp1 + k0 + 32);
        }
        #pragma unroll
        for (int kk = 0; kk < 2; kk++) {
            unsigned ka = a_base + kk * 32, kb = b_base + kk * 32;
            unsigned af[2][4], bf[4][4];
            #pragma unroll
            for (int mt = 0; mt < 2; mt++) LDSM4(af[mt], ka + mt * 16 * (RSE * 2));
            #pragma unroll
            for (int j = 0; j < 4; j++) LDSM4(bf[j], kb + j * 16 * (RSE * 2));
            #pragma unroll
            for (int mt = 0; mt < 2; mt++)
                #pragma unroll
                for (int nt = 0; nt < 8; nt++)
                    MMA16816(acc[mt][nt], af[mt],
                             bf[nt >> 1][(nt & 1) * 2 + 0], bf[nt >> 1][(nt & 1) * 2 + 1]);
        }
    }
    const int rr = lane >> 2, cc = (lane & 3) * 2;
    #pragma unroll
    for (int mt = 0; mt < 2; mt++) {
        int row = bm + wm + mt * 16 + rr;
        #pragma unroll
        for (int nt = 0; nt < 8; nt++) {
            int col = bn + wn + nt * 8 + cc;
            float2 lo = make_float2(acc[mt][nt][0], acc[mt][nt][1]);
            float2 hi = make_float2(acc[mt][nt][2], acc[mt][nt][3]);
            if (Cin) {
                float2 c0 = *(const float2*)(Cin + (size_t)row * D_ + col);
                float2 c1 = *(const float2*)(Cin + (size_t)(row + 8) * D_ + col);
                lo.x += c0.x; lo.y += c0.y; hi.x += c1.x; hi.y += c1.y;
            }
            *(float2*)(Cout + (size_t)row * D_ + col)       = lo;
            *(float2*)(Cout + (size_t)(row + 8) * D_ + col) = hi;
        }
    }
}

// ---------------- chunk prep: MMA phase 1 + forward substitution ------------
// dyn smem: stk 65 rows x 528B @0 (34320); Wl f32 64x65 @34320 (16640); gp @50960
#define PSTK 0
#define PWL  34320
#define PGP  50960
#define PREP_SMEM 51328
__global__ __launch_bounds__(256) void prep_kernel() {
    extern __shared__ char smc[];
    const unsigned sb = smem_u32(smc);
    float* Wl  = (float*)(smc + PWL);
    float* gps = (float*)(smc + PGP);
    const int tid = threadIdx.x, wid = tid >> 5, lane = tid & 31;
    const int n  = blockIdx.x & (N_ - 1);
    const int bh = blockIdx.x >> 7;
    const int b  = bh >> 2, h = bh & 3;
    if (tid <= C_) gps[tid] = g_gpow[h][tid];

    // ---- load 65 rows (t = n*C-1 .. n*C+63) of rkb into stk ----
    const __nv_bfloat16* gRkb = g_rkb + (size_t)bh * T_ * HD_;
    const int t0 = n * C_ - 1;
    {
        int r = tid >> 2, seg = (tid & 3) * 64;   // 64 bf16 = 128B per seg
        int grow = t0 + r; if (grow < 0) grow = 0;
        unsigned d = sb + PSTK + r * 528 + seg * 2;
        const __nv_bfloat16* s = gRkb + (size_t)grow * HD_ + seg;
        #pragma unroll
        for (int q = 0; q < 8; q++) CPA16(d + q * 16, s + q * 8);
        if (tid < 4) {
            unsigned d2 = sb + PSTK + 64 * 528 + tid * 128;
            const __nv_bfloat16* s2 = gRkb + (size_t)(t0 + 64) * HD_ + tid * 64;
            #pragma unroll
            for (int q = 0; q < 8; q++) CPA16(d2 + q * 16, s2 + q * 8);
        }
    }
    CPCOMMIT(); CPWAIT0();
    __syncthreads();
    if (t0 < 0 && tid < 32) *(uint4*)(smc + PSTK + tid * 16) = make_uint4(0,0,0,0);
    __syncthreads();

    // ---- phase 1: [wk(64); rk(64)] @ wk^T via HMMA ----
    // wk row i = stk row i; rk row i = stk row i+1; B (wk cols) = stk rows.
    float acc[8][4];
    #pragma unroll
    for (int nt = 0; nt < 8; nt++)
        #pragma unroll
        for (int q = 0; q < 4; q++) acc[nt][q] = 0.f;
    {
        const unsigned abase = sb + PSTK +
            ((wid & 3) * 16 + (lane & 15) + (wid >= 4 ? 1 : 0)) * 528 + (lane >> 4) * 16;
        const unsigned bbase = sb + PSTK +
            ((lane & 7) + ((lane >> 4) & 1) * 8) * 528 + ((lane >> 3) & 1) * 16;
        #pragma unroll
        for (int k = 0; k < 16; k++) {
            unsigned af[4], bf4[4][4];
            LDSM4(af, abase + k * 32);
            #pragma unroll
            for (int j = 0; j < 4; j++) LDSM4(bf4[j], bbase + j * 16 * 528 + k * 32);
            #pragma unroll
            for (int nt = 0; nt < 8; nt++)
                MMA16816(acc[nt], af,
                         bf4[nt >> 1][(nt & 1) * 2 + 0], bf4[nt >> 1][(nt & 1) * 2 + 1]);
        }
    }
    // epilogue: W (warps 0-3) -> Wl*L smem f32; R (warps 4-7) -> intra*L bf16 gmem
    size_t ib = ((size_t)(bh * N_ + n)) * C_;
    {
        const int rr = lane >> 2, cq = (lane & 3) * 2;
        const int i0 = (wid & 3) * 16 + rr;
        #pragma unroll
        for (int nt = 0; nt < 8; nt++) {
            int j = nt * 8 + cq;
            #pragma unroll
            for (int half = 0; half < 2; half++) {
                int i = i0 + half * 8;
                float v0 = acc[nt][half * 2 + 0], v1 = acc[nt][half * 2 + 1];
                float l0 = (j < i)     ? gps[i - j]     : 0.f;
                float l1 = (j + 1 < i) ? gps[i - j - 1] : 0.f;
                if (wid < 4) {
                    Wl[i * 65 + j]     = v0 * l0;
                    Wl[i * 65 + j + 1] = v1 * l1;
                } else {
                    *(__nv_bfloat162*)&g_intra_b[(ib + i) * C_ + j] =
                        __floats2bfloat162_rn(v0 * l0, v1 * l1);
                }
            }
        }
    }
    __syncthreads();

    // ---- phase 2: forward substitution (v, wk packed) + wkg^T emit ----
    const int c = tid;
    ull bvw[C_];
    const size_t wgbase = ((size_t)(bh * N_ + n) * HD_ + c) * C_;
    #pragma unroll
    for (int i2 = 0; i2 < C_ / 2; i2++) {
        int i = 2 * i2;
        float bv0 = g_v[((size_t)b * T_ + n * C_ + i) * D_ + h * HD_ + c];
        float bv1 = g_v[((size_t)b * T_ + n * C_ + i + 1) * D_ + h * HD_ + c];
        int tw0 = n * C_ + i - 1;
        float bw0 = (tw0 >= 0) ? g_rk[((size_t)bh * T_ + tw0) * HD_ + c] : 0.f;
        float bw1 = g_rk[((size_t)bh * T_ + tw0 + 1) * HD_ + c];
        bvw[i]     = pk2(bv0, bw0);
        bvw[i + 1] = pk2(bv1, bw1);
        __nv_bfloat162 wp;
        wp.x = __float2bfloat16(bw0 * gps[63 - i]);
        wp.y = __float2bfloat16(bw1 * gps[62 - i]);
        *(__nv_bfloat162*)&g_wkgT[wgbase + i] = wp;
    }
    #pragma unroll
    for (int i = 1; i < C_; i++) {
        ull a = 0ULL;
        #pragma unroll
        for (int j = 0; j < C_; j++) {
            if (j < i) {
                float m = Wl[i * 65 + j];
                a = fma2(pk2(m, m), bvw[j], a);
            }
        }
        bvw[i] = add2(bvw[i], a ^ SGN2);
    }
    #pragma unroll
    for (int i = 0; i < C_; i++) {
        float2 f = upk2(bvw[i]);
        g_vcorr [(ib + i) * HD_ + c] = f.x;
        g_wkcA_b[(ib + i) * HD_ + c] = __float2bfloat16(f.y);
    }
}

// ---------------- MMA chunk scan (unchanged from R5) ----------------
#define AST_OFF 0
#define AST_BUF 67584
#define WGT_OFF 135168
#define SB_OFF  172032
#define VNT_OFF 188928
#define INT_OFF 193536
#define VCO_OFF 202752
#define GP_OFF  211968
#define SCAN_SMEM 212480

__global__ void __launch_bounds__(256, 1) scan_mma_kernel() {
    extern __shared__ char smc[];
    const unsigned sb = smem_u32(smc);
    const int tid = threadIdx.x, wid = tid >> 5, lane = tid & 31;
    const int bh = blockIdx.y, c0 = blockIdx.x * 32;
    const int b = bh >> 2, h = bh & 3;
    float* gps = (float*)(smc + GP_OFF);
    if (tid <= C_) gps[tid] = g_gpow[h][tid];
    if (tid == C_ + 1) gps[C_ + 1] = g_alpha[h];

    const __nv_bfloat16* gWkc = g_wkcA_b + (size_t)bh * N_ * C_ * HD_;
    const __nv_bfloat16* gRk  = g_rkb    + (size_t)bh * T_ * HD_;
    const __nv_bfloat16* gWg  = g_wkgT   + (size_t)bh * N_ * HD_ * C_;
    const __nv_bfloat16* gIn  = g_intra_b+ (size_t)bh * N_ * C_ * C_;
    const float*         gVc  = g_vcorr  + (size_t)bh * N_ * C_ * HD_;

    auto copyG1 = [&](int n) {
        int r = tid >> 1, half = tid & 1;
        unsigned d = sb + AST_OFF + (n & 1) * AST_BUF + r * 528 + half * 256;
        const __nv_bfloat16* s = (r < 64)
            ? gWkc + ((size_t)n * C_ + r) * HD_ + half * 128
            : gRk  + ((size_t)n * C_ + (r - 64)) * HD_ + half * 128;
        #pragma unroll
        for (int q = 0; q < 16; q++) CPA16(d + q * 16, s + q * 8);
    };
    auto copyG2 = [&](int n) {
        unsigned d1 = sb + WGT_OFF + tid * 144;
        const __nv_bfloat16* s1 = gWg + ((size_t)n * HD_ + tid) * C_;
        #pragma unroll
        for (int q = 0; q < 8; q++) CPA16(d1 + q * 16, s1 + q * 8);
        int row = tid >> 2, ch = tid & 3;
        unsigned d2 = sb + INT_OFF + row * 144 + ch * 32;
        const __nv_bfloat16* s2 = gIn + ((size_t)n * C_ + row) * C_ + ch * 16;
        CPA16(d2, s2); CPA16(d2 + 16, s2 + 8);
        unsigned d3 = sb + VCO_OFF + row * 144 + ch * 32;
        const float* s3 = gVc + ((size_t)n * C_ + row) * HD_ + c0 + ch * 8;
        CPA16(d3, s3); CPA16(d3 + 16, s3 + 4);
    };

    const unsigned aA = sb + AST_OFF + (wid * 16 + (lane & 15)) * 528 + (lane >> 4) * 16;
    const unsigned bS = sb + SB_OFF + ((lane & 7) + ((lane >> 4) & 1) * 8) * 528 + ((lane >> 3) & 1) * 16;
    const unsigned aV = sb + VNT_OFF + (lane & 15) * 144 + (lane >> 4) * 16;
    const unsigned bW = sb + WGT_OFF + (wid * 32 + (lane & 7) + ((lane >> 4) & 1) * 8) * 144 + ((lane >> 3) & 1) * 16;
    const unsigned aI = sb + INT_OFF + ((wid & 3) * 16 + (lane & 15)) * 144 + (lane >> 4) * 16;
    const unsigned bV = sb + VNT_OFF + ((lane & 7) + ((lane >> 4) & 1) * 8) * 144 + ((lane >> 3) & 1) * 16;

    float Sacc[2][4][4] = {};
    copyG1(0); CPCOMMIT();
    copyG2(0); CPCOMMIT();

    for (int n = 0; n < N_; n++) {
        #pragma unroll
        for (int ct = 0; ct < 2; ct++)
            #pragma unroll
            for (int nt = 0; nt < 4; nt++) {
                int c = ct * 16 + (lane >> 2);
                int ks = wid * 32 + nt * 8 + (lane & 3) * 2;
                *(__nv_bfloat162*)(smc + SB_OFF + c * 528 + ks * 2) =
                    __floats2bfloat162_rn(Sacc[ct][nt][0], Sacc[ct][nt][1]);
                *(__nv_bfloat162*)(smc + SB_OFF + (c + 8) * 528 + ks * 2) =
                    __floats2bfloat162_rn(Sacc[ct][nt][2], Sacc[ct][nt][3]);
            }
        if (n + 1 < N_) copyG1(n + 1);
        CPCOMMIT();
        CPWAIT1();
        __syncthreads();

        float accA[4][4] = {};
        {
            unsigned ab = aA + (n & 1) * AST_BUF;
            #pragma unroll
            for (int k = 0; k < 16; k++) {
                unsigned af[4], b0[4], b1[4];
                LDSM4(af, ab + k * 32);
                LDSM4(b0, bS + k * 32);
                LDSM4(b1, bS + 8448 + k * 32);
                MMA16816(accA[0], af, b0[0], b0[1]);
                MMA16816(accA[1], af, b0[2], b0[3]);
                MMA16816(accA[2], af, b1[0], b1[1]);
                MMA16816(accA[3], af, b1[2], b1[3]);
            }
        }
        int r0 = (wid & 3) * 16 + (lane >> 2);
        if (wid < 4) {
            #pragma unroll
            for (int nt = 0; nt < 4; nt++) {
                int cc = nt * 8 + (lane & 3) * 2;
                float2 v0 = *(float2*)(smc + VCO_OFF + r0 * 144 + cc * 4);
                float2 v1 = *(float2*)(smc + VCO_OFF + (r0 + 8) * 144 + cc * 4);
                *(__nv_bfloat16*)(smc + VNT_OFF + cc * 144 + r0 * 2)       = __float2bfloat16(v0.x - accA[nt][0]);
                *(__nv_bfloat16*)(smc + VNT_OFF + (cc + 1) * 144 + r0 * 2) = __float2bfloat16(v0.y - accA[nt][1]);
                *(__nv_bfloat16*)(smc + VNT_OFF + cc * 144 + (r0 + 8) * 2)       = __float2bfloat16(v1.x - accA[nt][2]);
                *(__nv_bfloat16*)(smc + VNT_OFF + (cc + 1) * 144 + (r0 + 8) * 2) = __float2bfloat16(v1.y - accA[nt][3]);
            }
        } else {
            float g0 = gps[r0], g1 = gps[r0 + 8];
            #pragma unroll
            for (int nt = 0; nt < 4; nt++) {
                accA[nt][0] *= g0; accA[nt][1] *= g0;
                accA[nt][2] *= g1; accA[nt][3] *= g1;
            }
        }
        __syncthreads();

        if (wid >= 4) {
            #pragma unroll
            for (int k = 0; k < 4; k++) {
                unsigned ai[4], v0[4], v1[4];
                LDSM4(ai, aI + k * 32);
                LDSM4(v0, bV + k * 32);
                LDSM4(v1, bV + 2304 + k * 32);
                MMA16816(accA[0], ai, v0[0], v0[1]);
                MMA16816(accA[1], ai, v0[2], v0[3]);
                MMA16816(accA[2], ai, v1[0], v1[1]);
                MMA16816(accA[3], ai, v1[2], v1[3]);
            }
            float al = gps[C_ + 1];
            size_t ob = ((size_t)b * T_ + n * C_) * D_ + h * HD_ + c0;
            #pragma unroll
            for (int nt = 0; nt < 4; nt++) {
                int cc = nt * 8 + (lane & 3) * 2;
                *(__nv_bfloat162*)(g_ob + ob + (size_t)r0 * D_ + cc) =
                    __floats2bfloat162_rn(accA[nt][0] * al, accA[nt][1] * al);
                *(__nv_bfloat162*)(g_ob + ob + (size_t)(r0 + 8) * D_ + cc) =
                    __floats2bfloat162_rn(accA[nt][2] * al, accA[nt][3] * al);
            }
        }

        {
            float gC = gps[C_];
            #pragma unroll
            for (int ct = 0; ct < 2; ct++)
                #pragma unroll
                for (int nt = 0; nt < 4; nt++)
                    #pragma unroll
                    for (int q = 0; q < 4; q++) Sacc[ct][nt][q] *= gC;
            #pragma unroll
            for (int k = 0; k < 4; k++) {
                unsigned a0[4], a1[4], w0[4], w1[4];
                LDSM4(a0, aV + k * 32);
                LDSM4(a1, aV + 2304 + k * 32);
                LDSM4(w0, bW + k * 32);
                LDSM4(w1, bW + 2304 + k * 32);
                MMA16816(Sacc[0][0], a0, w0[0], w0[1]);
                MMA16816(Sacc[0][1], a0, w0[2], w0[3]);
                MMA16816(Sacc[0][2], a0, w1[0], w1[1]);
                MMA16816(Sacc[0][3], a0, w1[2], w1[3]);
                MMA16816(Sacc[1][0], a1, w0[0], w0[1]);
                MMA16816(Sacc[1][1], a1, w0[2], w0[3]);
                MMA16816(Sacc[1][2], a1, w1[0], w1[1]);
                MMA16816(Sacc[1][3], a1, w1[2], w1[3]);
            }
        }
        __syncthreads();
        if (n + 1 < N_) copyG2(n + 1);
        CPCOMMIT();
    }
}

// ---------------- launch ----------------
extern "C" void kernel_launch(void* const* d_in, const int* in_sizes, int n_in,
                              void* d_out, int out_size) {
    const float* x     = (const float*)d_in[0];
    const float* Ww    = (const float*)d_in[1];
    const float* Wr    = (const float*)d_in[2];
    const float* decay = (const float*)d_in[3];
    const float* lalp  = (const float*)d_in[4];
    float* out = (float*)d_out;

    cudaFuncSetAttribute(scan_mma_kernel, cudaFuncAttributeMaxDynamicSharedMemorySize,
                         SCAN_SMEM);
    cudaFuncSetAttribute(prep_kernel, cudaFuncAttributeMaxDynamicSharedMemorySize,
                         PREP_SMEM);

    void *pv = nullptr, *pxb = nullptr, *pob = nullptr, *pwwb = nullptr, *pwrb = nullptr;
    cudaGetSymbolAddress(&pv, g_v);
    cudaGetSymbolAddress(&pxb, g_xb);
    cudaGetSymbolAddress(&pob, g_ob);
    cudaGetSymbolAddress(&pwwb, g_Wwb);
    cudaGetSymbolAddress(&pwrb, g_Wrb);

    const size_t NW = (size_t)D_ * D_;

    setup_kernel<<<1, 32>>>(decay, lalp);
    rk_kernel<<<(B_ * T_ * H_) / 8, 256>>>(x);
    conv_bf16<<<(int)(NW / 2048), 256>>>(Ww, (__nv_bfloat16*)pwwb);
    gemm_bf16_tn<<<dim3(D_ / 128, (B_ * T_) / 128), 256>>>(
        (const __nv_bfloat16*)pxb, (const __nv_bfloat16*)pwwb, nullptr, (float*)pv);
    prep_kernel<<<BH_ * N_, 256, PREP_SMEM>>>();
    scan_mma_kernel<<<dim3(8, BH_), 256, SCAN_SMEM>>>();
    conv_bf16<<<(int)(NW / 2048), 256>>>(Wr, (__nv_bfloat16*)pwrb);
    gemm_bf16_tn<<<dim3(D_ / 128, (B_ * T_) / 128), 256>>>(
        (const __nv_bfloat16*)pob, (const __nv_bfloat16*)pwrb, x, out);
}

// round 10
// speedup vs baseline: 2.4277x; 1.1727x over previous
#include <cuda_runtime.h>
#include <cuda_bf16.h>

#define B_    2
#define T_    8192
#define D_    1024
#define H_    4
#define HD_   256
#define C_    64
#define N_    128
#define BH_   8

typedef unsigned long long ull;

__device__ __forceinline__ ull pk2(float a, float b) {
    ull r; asm("mov.b64 %0, {%1, %2};" : "=l"(r) : "f"(a), "f"(b)); return r;
}
__device__ __forceinline__ float2 upk2(ull v) {
    float2 f; asm("mov.b64 {%0, %1}, %2;" : "=f"(f.x), "=f"(f.y) : "l"(v)); return f;
}
__device__ __forceinline__ ull fma2(ull a, ull b, ull c) {
    ull d; asm("fma.rn.f32x2 %0, %1, %2, %3;" : "=l"(d) : "l"(a), "l"(b), "l"(c)); return d;
}
__device__ __forceinline__ ull add2(ull a, ull b) {
    ull d; asm("add.rn.f32x2 %0, %1, %2;" : "=l"(d) : "l"(a), "l"(b)); return d;
}
#define SGN2 0x8000000080000000ULL

__device__ __forceinline__ unsigned smem_u32(const void* p) {
    unsigned a;
    asm("{ .reg .u64 t; cvta.to.shared.u64 t, %1; cvt.u32.u64 %0, t; }" : "=r"(a) : "l"(p));
    return a;
}
#define LDSM4(r, addr) \
    asm volatile("ldmatrix.sync.aligned.m8n8.x4.shared.b16 {%0,%1,%2,%3}, [%4];" \
        : "=r"((r)[0]), "=r"((r)[1]), "=r"((r)[2]), "=r"((r)[3]) : "r"(addr))
#define MMA16816(d, a, b0v, b1v) \
    asm volatile("mma.sync.aligned.m16n8k16.row.col.f32.bf16.bf16.f32 " \
        "{%0,%1,%2,%3}, {%4,%5,%6,%7}, {%8,%9}, {%0,%1,%2,%3};" \
        : "+f"((d)[0]), "+f"((d)[1]), "+f"((d)[2]), "+f"((d)[3]) \
        : "r"((a)[0]), "r"((a)[1]), "r"((a)[2]), "r"((a)[3]), "r"(b0v), "r"(b1v))
#define CPA16(dst, src) \
    asm volatile("cp.async.cg.shared.global [%0], [%1], 16;" :: "r"(dst), "l"(src))
#define CPCOMMIT() asm volatile("cp.async.commit_group;")
#define CPWAIT1()  asm volatile("cp.async.wait_group 1;")
#define CPWAIT0()  asm volatile("cp.async.wait_group 0;")

// ---------------- device scratch ----------------
__device__ float g_v[(size_t)B_ * T_ * D_];
__device__ float g_rk[(size_t)BH_ * T_ * HD_];
__device__ float g_vcorr[(size_t)BH_ * N_ * C_ * HD_];
__device__ float g_gpow[H_][C_ + 1];
__device__ float g_alpha[H_];
__device__ __nv_bfloat16 g_xb [(size_t)B_ * T_ * D_];
__device__ __nv_bfloat16 g_ob [(size_t)B_ * T_ * D_];
__device__ __nv_bfloat16 g_Wwb[(size_t)D_ * D_];
__device__ __nv_bfloat16 g_Wrb[(size_t)D_ * D_];
__device__ __nv_bfloat16 g_rkb   [(size_t)BH_ * T_ * HD_];
__device__ __nv_bfloat16 g_wkcA_b[(size_t)BH_ * N_ * C_ * HD_];
__device__ __nv_bfloat16 g_intra_b[(size_t)BH_ * N_ * C_ * C_];
__device__ __nv_bfloat16 g_wkgT  [(size_t)BH_ * N_ * HD_ * C_];

__global__ void setup_kernel(const float* __restrict__ decay,
                             const float* __restrict__ log_alpha) {
    int h = threadIdx.x;
    if (h < H_) {
        float g = 1.f / (1.f + expf(-decay[h]));
        g_alpha[h] = expf(log_alpha[h]);
        float p = 1.f;
        for (int i = 0; i <= C_; i++) { g_gpow[h][i] = p; p *= g; }
    }
}

__global__ __launch_bounds__(256) void conv_bf16(const float* __restrict__ in,
                                                 __nv_bfloat16* __restrict__ out) {
    size_t i = ((size_t)blockIdx.x * 256 + threadIdx.x) * 8;
    float4 a = *(const float4*)(in + i);
    float4 b = *(const float4*)(in + i + 4);
    __nv_bfloat162 r0 = __floats2bfloat162_rn(a.x, a.y);
    __nv_bfloat162 r1 = __floats2bfloat162_rn(a.z, a.w);
    __nv_bfloat162 r2 = __floats2bfloat162_rn(b.x, b.y);
    __nv_bfloat162 r3 = __floats2bfloat162_rn(b.z, b.w);
    uint4 pk;
    pk.x = *(unsigned*)&r0; pk.y = *(unsigned*)&r1;
    pk.z = *(unsigned*)&r2; pk.w = *(unsigned*)&r3;
    *(uint4*)(out + i) = pk;
}

// rk normalize (writes f32 + bf16), fused x -> g_xb bf16
__global__ __launch_bounds__(256) void rk_kernel(const float* __restrict__ x) {
    int warp = threadIdx.x >> 5, lane = threadIdx.x & 31;
    int row = blockIdx.x * 8 + warp;
    int h  = row & (H_ - 1);
    int bt = row >> 2;
    const float* xp = x + (size_t)bt * D_ + h * HD_ + lane * 8;
    float4 v0 = *(const float4*)(xp);
    float4 v1 = *(const float4*)(xp + 4);
    {
        __nv_bfloat162 q0 = __floats2bfloat162_rn(v0.x, v0.y);
        __nv_bfloat162 q1 = __floats2bfloat162_rn(v0.z, v0.w);
        __nv_bfloat162 q2 = __floats2bfloat162_rn(v1.x, v1.y);
        __nv_bfloat162 q3 = __floats2bfloat162_rn(v1.z, v1.w);
        uint4 pk;
        pk.x = *(unsigned*)&q0; pk.y = *(unsigned*)&q1;
        pk.z = *(unsigned*)&q2; pk.w = *(unsigned*)&q3;
        *(uint4*)(g_xb + (size_t)bt * D_ + h * HD_ + lane * 8) = pk;
    }
    float ss = v0.x*v0.x + v0.y*v0.y + v0.z*v0.z + v0.w*v0.w
             + v1.x*v1.x + v1.y*v1.y + v1.z*v1.z + v1.w*v1.w;
    #pragma unroll
    for (int o = 16; o; o >>= 1) ss += __shfl_xor_sync(0xffffffffu, ss, o);
    float inv = 1.f / fmaxf(sqrtf(ss), 1e-12f);
    int b = bt >> 13, t = bt & (T_ - 1);
    size_t base = ((size_t)(b * H_ + h) * T_ + t) * HD_ + lane * 8;
    float4 o0 = make_float4(v0.x*inv, v0.y*inv, v0.z*inv, v0.w*inv);
    float4 o1 = make_float4(v1.x*inv, v1.y*inv, v1.z*inv, v1.w*inv);
    *(float4*)(g_rk + base)     = o0;
    *(float4*)(g_rk + base + 4) = o1;
    __nv_bfloat162 q0 = __floats2bfloat162_rn(o0.x, o0.y);
    __nv_bfloat162 q1 = __floats2bfloat162_rn(o0.z, o0.w);
    __nv_bfloat162 q2 = __floats2bfloat162_rn(o1.x, o1.y);
    __nv_bfloat162 q3 = __floats2bfloat162_rn(o1.z, o1.w);
    uint4 pk;
    pk.x = *(unsigned*)&q0; pk.y = *(unsigned*)&q1;
    pk.z = *(unsigned*)&q2; pk.w = *(unsigned*)&q3;
    *(uint4*)(g_rkb + base) = pk;
}

// ---------------- bf16 GEMM (TN), cp.async double-buffered ----------------
#define RSE 40
#define STG_B (128 * RSE * 2)   // bytes per stage per matrix (10240)
__global__ __launch_bounds__(256, 2) void gemm_bf16_tn(const __nv_bfloat16* __restrict__ A,
                                                       const __nv_bfloat16* __restrict__ W,
                                                       const float* __restrict__ Cin,
                                                       float* __restrict__ Cout) {
    __shared__ __nv_bfloat16 As[2][128 * RSE];
    __shared__ __nv_bfloat16 Bs[2][128 * RSE];
    const int tid = threadIdx.x;
    const int bm = blockIdx.y * 128, bn = blockIdx.x * 128;
    const int wid = tid >> 5, lane = tid & 31;
    const int wm = (wid & 3) * 32, wn = (wid >> 2) * 64;
    const int lr = tid >> 2, lk = (tid & 3) * 8;
    const __nv_bfloat16* Ap0 = A + (size_t)(bm + lr) * D_ + lk;
    const __nv_bfloat16* Ap1 = A + (size_t)(bm + lr + 64) * D_ + lk;
    const __nv_bfloat16* Wp0 = W + (size_t)(bn + lr) * D_ + lk;
    const __nv_bfloat16* Wp1 = W + (size_t)(bn + lr + 64) * D_ + lk;
    const unsigned dA = smem_u32(&As[0][lr * RSE + lk]);
    const unsigned dB = smem_u32(&Bs[0][lr * RSE + lk]);
    const unsigned a_base = smem_u32(As) +
        (unsigned)((wm + (lane & 7) + ((lane >> 3) & 1) * 8) * (RSE * 2) + (lane >> 4) * 16);
    const unsigned b_base = smem_u32(Bs) +
        (unsigned)((wn + (lane & 7) + ((lane >> 4) & 1) * 8) * (RSE * 2) + ((lane >> 3) & 1) * 16);

    float acc[2][8][4];
    #pragma unroll
    for (int mt = 0; mt < 2; mt++)
        #pragma unroll
        for (int nt = 0; nt < 8; nt++)
            #pragma unroll
            for (int q = 0; q < 4; q++) acc[mt][nt][q] = 0.f;

    auto loadStage = [&](int s, int k0) {
        CPA16(dA + s * STG_B, Ap0 + k0);
        CPA16(dA + s * STG_B + 64 * RSE * 2, Ap1 + k0);
        CPA16(dB + s * STG_B, Wp0 + k0);
        CPA16(dB + s * STG_B + 64 * RSE * 2, Wp1 + k0);
    };

    loadStage(0, 0);  CPCOMMIT();
    loadStage(1, 32); CPCOMMIT();

    for (int i = 0; i < 32; i++) {
        if (i < 31) { CPWAIT1(); } else { CPWAIT0(); }
        __syncthreads();
        const unsigned sa = a_base + (i & 1) * STG_B;
        const unsigned sbb = b_base + (i & 1) * STG_B;
        #pragma unroll
        for (int kk = 0; kk < 2; kk++) {
            unsigned ka = sa + kk * 32, kb = sbb + kk * 32;
            unsigned af[2][4], bf[4][4];
            #pragma unroll
            for (int mt = 0; mt < 2; mt++) LDSM4(af[mt], ka + mt * 16 * (RSE * 2));
            #pragma unroll
            for (int j = 0; j < 4; j++) LDSM4(bf[j], kb + j * 16 * (RSE * 2));
            #pragma unroll
            for (int mt = 0; mt < 2; mt++)
                #pragma unroll
                for (int nt = 0; nt < 8; nt++)
                    MMA16816(acc[mt][nt], af[mt],
                             bf[nt >> 1][(nt & 1) * 2 + 0], bf[nt >> 1][(nt & 1) * 2 + 1]);
        }
        __syncthreads();
        if (i + 2 < 32) { loadStage(i & 1, (i + 2) * 32); CPCOMMIT(); }
    }

    const int rr = lane >> 2, cc = (lane & 3) * 2;
    #pragma unroll
    for (int mt = 0; mt < 2; mt++) {
        int row = bm + wm + mt * 16 + rr;
        #pragma unroll
        for (int nt = 0; nt < 8; nt++) {
            int col = bn + wn + nt * 8 + cc;
            float2 lo = make_float2(acc[mt][nt][0], acc[mt][nt][1]);
            float2 hi = make_float2(acc[mt][nt][2], acc[mt][nt][3]);
            if (Cin) {
                float2 c0 = *(const float2*)(Cin + (size_t)row * D_ + col);
                float2 c1 = *(const float2*)(Cin + (size_t)(row + 8) * D_ + col);
                lo.x += c0.x; lo.y += c0.y; hi.x += c1.x; hi.y += c1.y;
            }
            *(float2*)(Cout + (size_t)row * D_ + col)       = lo;
            *(float2*)(Cout + (size_t)(row + 8) * D_ + col) = hi;
        }
    }
}

// ---------------- chunk prep: MMA phase 1 + forward substitution ------------
#define PSTK 0
#define PWL  34320
#define PGP  50960
#define PREP_SMEM 51328
__global__ __launch_bounds__(256) void prep_kernel() {
    extern __shared__ char smc[];
    const unsigned sb = smem_u32(smc);
    float* Wl  = (float*)(smc + PWL);
    float* gps = (float*)(smc + PGP);
    const int tid = threadIdx.x, wid = tid >> 5, lane = tid & 31;
    const int n  = blockIdx.x & (N_ - 1);
    const int bh = blockIdx.x >> 7;
    const int b  = bh >> 2, h = bh & 3;
    if (tid <= C_) gps[tid] = g_gpow[h][tid];

    const __nv_bfloat16* gRkb = g_rkb + (size_t)bh * T_ * HD_;
    const int t0 = n * C_ - 1;
    {
        int r = tid >> 2, seg = (tid & 3) * 64;
        int grow = t0 + r; if (grow < 0) grow = 0;
        unsigned d = sb + PSTK + r * 528 + seg * 2;
        const __nv_bfloat16* s = gRkb + (size_t)grow * HD_ + seg;
        #pragma unroll
        for (int q = 0; q < 8; q++) CPA16(d + q * 16, s + q * 8);
        if (tid < 4) {
            unsigned d2 = sb + PSTK + 64 * 528 + tid * 128;
            const __nv_bfloat16* s2 = gRkb + (size_t)(t0 + 64) * HD_ + tid * 64;
            #pragma unroll
            for (int q = 0; q < 8; q++) CPA16(d2 + q * 16, s2 + q * 8);
        }
    }
    CPCOMMIT(); CPWAIT0();
    __syncthreads();
    if (t0 < 0 && tid < 32) *(uint4*)(smc + PSTK + tid * 16) = make_uint4(0,0,0,0);
    __syncthreads();

    float acc[8][4];
    #pragma unroll
    for (int nt = 0; nt < 8; nt++)
        #pragma unroll
        for (int q = 0; q < 4; q++) acc[nt][q] = 0.f;
    {
        const unsigned abase = sb + PSTK +
            ((wid & 3) * 16 + (lane & 15) + (wid >= 4 ? 1 : 0)) * 528 + (lane >> 4) * 16;
        const unsigned bbase = sb + PSTK +
            ((lane & 7) + ((lane >> 4) & 1) * 8) * 528 + ((lane >> 3) & 1) * 16;
        #pragma unroll
        for (int k = 0; k < 16; k++) {
            unsigned af[4], bf4[4][4];
            LDSM4(af, abase + k * 32);
            #pragma unroll
            for (int j = 0; j < 4; j++) LDSM4(bf4[j], bbase + j * 16 * 528 + k * 32);
            #pragma unroll
            for (int nt = 0; nt < 8; nt++)
                MMA16816(acc[nt], af,
                         bf4[nt >> 1][(nt & 1) * 2 + 0], bf4[nt >> 1][(nt & 1) * 2 + 1]);
        }
    }
    size_t ib = ((size_t)(bh * N_ + n)) * C_;
    {
        const int rr = lane >> 2, cq = (lane & 3) * 2;
        const int i0 = (wid & 3) * 16 + rr;
        #pragma unroll
        for (int nt = 0; nt < 8; nt++) {
            int j = nt * 8 + cq;
            #pragma unroll
            for (int half = 0; half < 2; half++) {
                int i = i0 + half * 8;
                float v0 = acc[nt][half * 2 + 0], v1 = acc[nt][half * 2 + 1];
                float l0 = (j < i)     ? gps[i - j]     : 0.f;
                float l1 = (j + 1 < i) ? gps[i - j - 1] : 0.f;
                if (wid < 4) {
                    Wl[i * 65 + j]     = v0 * l0;
                    Wl[i * 65 + j + 1] = v1 * l1;
                } else {
                    *(__nv_bfloat162*)&g_intra_b[(ib + i) * C_ + j] =
                        __floats2bfloat162_rn(v0 * l0, v1 * l1);
                }
            }
        }
    }
    __syncthreads();

    const int c = tid;
    ull bvw[C_];
    const size_t wgbase = ((size_t)(bh * N_ + n) * HD_ + c) * C_;
    #pragma unroll
    for (int i2 = 0; i2 < C_ / 2; i2++) {
        int i = 2 * i2;
        float bv0 = g_v[((size_t)b * T_ + n * C_ + i) * D_ + h * HD_ + c];
        float bv1 = g_v[((size_t)b * T_ + n * C_ + i + 1) * D_ + h * HD_ + c];
        int tw0 = n * C_ + i - 1;
        float bw0 = (tw0 >= 0) ? g_rk[((size_t)bh * T_ + tw0) * HD_ + c] : 0.f;
        float bw1 = g_rk[((size_t)bh * T_ + tw0 + 1) * HD_ + c];
        bvw[i]     = pk2(bv0, bw0);
        bvw[i + 1] = pk2(bv1, bw1);
        __nv_bfloat162 wp;
        wp.x = __float2bfloat16(bw0 * gps[63 - i]);
        wp.y = __float2bfloat16(bw1 * gps[62 - i]);
        *(__nv_bfloat162*)&g_wkgT[wgbase + i] = wp;
    }
    #pragma unroll
    for (int i = 1; i < C_; i++) {
        ull a = 0ULL;
        #pragma unroll
        for (int j = 0; j < C_; j++) {
            if (j < i) {
                float m = Wl[i * 65 + j];
                a = fma2(pk2(m, m), bvw[j], a);
            }
        }
        bvw[i] = add2(bvw[i], a ^ SGN2);
    }
    #pragma unroll
    for (int i = 0; i < C_; i++) {
        float2 f = upk2(bvw[i]);
        g_vcorr [(ib + i) * HD_ + c] = f.x;
        g_wkcA_b[(ib + i) * HD_ + c] = __float2bfloat16(f.y);
    }
}

// ---------------- MMA chunk scan: 128 CTAs (8 bh x 16 col-slabs of 16) ------
#define AST_OFF 0
#define AST_BUF 67584
#define WGT_OFF 135168
#define SB_OFF  172032
#define VNT_OFF 180480
#define INT_OFF 182784
#define VCO_OFF 192000
#define GP_OFF  201216
#define SCAN_SMEM 201728

__global__ void __launch_bounds__(256, 1) scan_mma_kernel() {
    extern __shared__ char smc[];
    const unsigned sb = smem_u32(smc);
    const int tid = threadIdx.x, wid = tid >> 5, lane = tid & 31;
    const int bh = blockIdx.y, c0 = blockIdx.x * 16;
    const int b = bh >> 2, h = bh & 3;
    float* gps = (float*)(smc + GP_OFF);
    if (tid <= C_) gps[tid] = g_gpow[h][tid];
    if (tid == C_ + 1) gps[C_ + 1] = g_alpha[h];

    const __nv_bfloat16* gWkc = g_wkcA_b + (size_t)bh * N_ * C_ * HD_;
    const __nv_bfloat16* gRk  = g_rkb    + (size_t)bh * T_ * HD_;
    const __nv_bfloat16* gWg  = g_wkgT   + (size_t)bh * N_ * HD_ * C_;
    const __nv_bfloat16* gIn  = g_intra_b+ (size_t)bh * N_ * C_ * C_;
    const float*         gVc  = g_vcorr  + (size_t)bh * N_ * C_ * HD_;

    auto copyG1 = [&](int n) {
        int r = tid >> 1, half = tid & 1;
        unsigned d = sb + AST_OFF + (n & 1) * AST_BUF + r * 528 + half * 256;
        const __nv_bfloat16* s = (r < 64)
            ? gWkc + ((size_t)n * C_ + r) * HD_ + half * 128
            : gRk  + ((size_t)n * C_ + (r - 64)) * HD_ + half * 128;
        #pragma unroll
        for (int q = 0; q < 16; q++) CPA16(d + q * 16, s + q * 8);
    };
    auto copyG2 = [&](int n) {
        unsigned d1 = sb + WGT_OFF + tid * 144;
        const __nv_bfloat16* s1 = gWg + ((size_t)n * HD_ + tid) * C_;
        #pragma unroll
        for (int q = 0; q < 8; q++) CPA16(d1 + q * 16, s1 + q * 8);
        int row = tid >> 2, ch = tid & 3;
        unsigned d2 = sb + INT_OFF + row * 144 + ch * 32;
        const __nv_bfloat16* s2 = gIn + ((size_t)n * C_ + row) * C_ + ch * 16;
        CPA16(d2, s2); CPA16(d2 + 16, s2 + 8);
        unsigned d3 = sb + VCO_OFF + row * 144 + ch * 16;
        const float* s3 = gVc + ((size_t)n * C_ + row) * HD_ + c0 + ch * 4;
        CPA16(d3, s3);
    };

    const unsigned aA = sb + AST_OFF + (wid * 16 + (lane & 15)) * 528 + (lane >> 4) * 16;
    const unsigned bS = sb + SB_OFF + ((lane & 7) + ((lane >> 4) & 1) * 8) * 528 + ((lane >> 3) & 1) * 16;
    const unsigned aV = sb + VNT_OFF + (lane & 15) * 144 + (lane >> 4) * 16;
    const unsigned bW = sb + WGT_OFF + (wid * 32 + (lane & 7) + ((lane >> 4) & 1) * 8) * 144 + ((lane >> 3) & 1) * 16;
    const unsigned aI = sb + INT_OFF + ((wid & 3) * 16 + (lane & 15)) * 144 + (lane >> 4) * 16;
    const unsigned bV = sb + VNT_OFF + ((lane & 7) + ((lane >> 4) & 1) * 8) * 144 + ((lane >> 3) & 1) * 16;

    float Sacc[4][4] = {};      // S^T: 16 c-rows x 32 ks (warp wid: ks in [32w,32w+32))
    copyG1(0); CPCOMMIT();
    copyG2(0); CPCOMMIT();

    for (int n = 0; n < N_; n++) {
        // Sb[c][ks] = bf16(S^T) from accumulators (16 rows x 256 ks)
        #pragma unroll
        for (int nt = 0; nt < 4; nt++) {
            int c = lane >> 2;
            int ks = wid * 32 + nt * 8 + (lane & 3) * 2;
            *(__nv_bfloat162*)(smc + SB_OFF + c * 528 + ks * 2) =
                __floats2bfloat162_rn(Sacc[nt][0], Sacc[nt][1]);
            *(__nv_bfloat162*)(smc + SB_OFF + (c + 8) * 528 + ks * 2) =
                __floats2bfloat162_rn(Sacc[nt][2], Sacc[nt][3]);
        }
        if (n + 1 < N_) copyG1(n + 1);
        CPCOMMIT();
        CPWAIT1();
        __syncthreads();

        // phase A: [wkc;rk](128x256) @ S(256x16) — warp rows 16*wid
        float accA[2][4] = {};
        {
            unsigned ab = aA + (n & 1) * AST_BUF;
            #pragma unroll
            for (int k = 0; k < 16; k++) {
                unsigned af[4], b0[4];
                LDSM4(af, ab + k * 32);
                LDSM4(b0, bS + k * 32);
                MMA16816(accA[0], af, b0[0], b0[1]);
                MMA16816(accA[1], af, b0[2], b0[3]);
            }
        }
        int r0 = (wid & 3) * 16 + (lane >> 2);
        if (wid < 4) {     // v_new = vco - t1; write v_new^T bf16
            #pragma unroll
            for (int nt = 0; nt < 2; nt++) {
                int cc = nt * 8 + (lane & 3) * 2;
                float2 v0 = *(float2*)(smc + VCO_OFF + r0 * 144 + cc * 4);
                float2 v1 = *(float2*)(smc + VCO_OFF + (r0 + 8) * 144 + cc * 4);
                *(__nv_bfloat16*)(smc + VNT_OFF + cc * 144 + r0 * 2)       = __float2bfloat16(v0.x - accA[nt][0]);
                *(__nv_bfloat16*)(smc + VNT_OFF + (cc + 1) * 144 + r0 * 2) = __float2bfloat16(v0.y - accA[nt][1]);
                *(__nv_bfloat16*)(smc + VNT_OFF + cc * 144 + (r0 + 8) * 2)       = __float2bfloat16(v1.x - accA[nt][2]);
                *(__nv_bfloat16*)(smc + VNT_OFF + (cc + 1) * 144 + (r0 + 8) * 2) = __float2bfloat16(v1.y - accA[nt][3]);
            }
        } else {           // orr *= gamma^i
            float g0 = gps[r0], g1 = gps[r0 + 8];
            #pragma unroll
            for (int nt = 0; nt < 2; nt++) {
                accA[nt][0] *= g0; accA[nt][1] *= g0;
                accA[nt][2] *= g1; accA[nt][3] *= g1;
            }
        }
        __syncthreads();

        // phase C (warps 4-7): o = orr*g + intra @ v_new; write alpha*o bf16
        if (wid >= 4) {
            #pragma unroll
            for (int k = 0; k < 4; k++) {
                unsigned ai[4], v0[4];
                LDSM4(ai, aI + k * 32);
                LDSM4(v0, bV + k * 32);
                MMA16816(accA[0], ai, v0[0], v0[1]);
                MMA16816(accA[1], ai, v0[2], v0[3]);
            }
            float al = gps[C_ + 1];
            size_t ob = ((size_t)b * T_ + n * C_) * D_ + h * HD_ + c0;
            #pragma unroll
            for (int nt = 0; nt < 2; nt++) {
                int cc = nt * 8 + (lane & 3) * 2;
                *(__nv_bfloat162*)(g_ob + ob + (size_t)r0 * D_ + cc) =
                    __floats2bfloat162_rn(accA[nt][0] * al, accA[nt][1] * al);
                *(__nv_bfloat162*)(g_ob + ob + (size_t)(r0 + 8) * D_ + cc) =
                    __floats2bfloat162_rn(accA[nt][2] * al, accA[nt][3] * al);
            }
        }

        // phase D: S^T = gC*S^T + v_new^T(16x64) @ wkg(64x256) — warp ks 32*wid
        {
            float gC = gps[C_];
            #pragma unroll
            for (int nt = 0; nt < 4; nt++)
                #pragma unroll
                for (int q = 0; q < 4; q++) Sacc[nt][q] *= gC;
            #pragma unroll
            for (int k = 0; k < 4; k++) {
                unsigned a0[4], w0[4], w1[4];
                LDSM4(a0, aV + k * 32);
                LDSM4(w0, bW + k * 32);
                LDSM4(w1, bW + 2304 + k * 32);
                MMA16816(Sacc[0], a0, w0[0], w0[1]);
                MMA16816(Sacc[1], a0, w0[2], w0[3]);
                MMA16816(Sacc[2], a0, w1[0], w1[1]);
                MMA16816(Sacc[3], a0, w1[2], w1[3]);
            }
        }
        __syncthreads();
        if (n + 1 < N_) copyG2(n + 1);
        CPCOMMIT();
    }
}

// ---------------- launch ----------------
extern "C" void kernel_launch(void* const* d_in, const int* in_sizes, int n_in,
                              void* d_out, int out_size) {
    const float* x     = (const float*)d_in[0];
    const float* Ww    = (const float*)d_in[1];
    const float* Wr    = (const float*)d_in[2];
    const float* decay = (const float*)d_in[3];
    const float* lalp  = (const float*)d_in[4];
    float* out = (float*)d_out;

    cudaFuncSetAttribute(scan_mma_kernel, cudaFuncAttributeMaxDynamicSharedMemorySize,
                         SCAN_SMEM);
    cudaFuncSetAttribute(prep_kernel, cudaFuncAttributeMaxDynamicSharedMemorySize,
                         PREP_SMEM);

    void *pv = nullptr, *pxb = nullptr, *pob = nullptr, *pwwb = nullptr, *pwrb = nullptr;
    cudaGetSymbolAddress(&pv, g_v);
    cudaGetSymbolAddress(&pxb, g_xb);
    cudaGetSymbolAddress(&pob, g_ob);
    cudaGetSymbolAddress(&pwwb, g_Wwb);
    cudaGetSymbolAddress(&pwrb, g_Wrb);

    const size_t NW = (size_t)D_ * D_;

    setup_kernel<<<1, 32>>>(decay, lalp);
    rk_kernel<<<(B_ * T_ * H_) / 8, 256>>>(x);
    conv_bf16<<<(int)(NW / 2048), 256>>>(Ww, (__nv_bfloat16*)pwwb);
    conv_bf16<<<(int)(NW / 2048), 256>>>(Wr, (__nv_bfloat16*)pwrb);
    gemm_bf16_tn<<<dim3(D_ / 128, (B_ * T_) / 128), 256>>>(
        (const __nv_bfloat16*)pxb, (const __nv_bfloat16*)pwwb, nullptr, (float*)pv);
    prep_kernel<<<BH_ * N_, 256, PREP_SMEM>>>();
    scan_mma_kernel<<<dim3(16, BH_), 256, SCAN_SMEM>>>();
    gemm_bf16_tn<<<dim3(D_ / 128, (B_ * T_) / 128), 256>>>(
        (const __nv_bfloat16*)pob, (const __nv_bfloat16*)pwrb, x, out);
}